// round 1
// baseline (speedup 1.0000x reference)
#include <cuda_runtime.h>
#include <math.h>

#define H       100
#define NNODES  1024    // N = B*L
#define BATCH   64
#define LSEQ    16
#define EDGES   2048
#define NNODE   40000
#define H4      25      // H/4 float4s per row

// ---- scratch (no allocations allowed) ----
__device__ float d_h  [NNODES * H];
__device__ float d_m  [NNODES * H];
__device__ float d_agg[NNODES * H];
__device__ float d_v  [NNODES * H];   // h after GRU  (== v flattened)
__device__ float d_vt [NNODES * H];   // v @ Wt^T + bt
__device__ float d_sh [BATCH  * H];   // s_h

// ------------------------------------------------------------------
// K1: h = embed[x];  m = h @ ggc_w[0];  agg = 0
// one block per node, 128 threads (100 active)
// ------------------------------------------------------------------
__global__ void k1_gather_m(const int* __restrict__ x,
                            const float* __restrict__ embed,
                            const float* __restrict__ ggc)
{
    int i = blockIdx.x;
    int t = threadIdx.x;
    __shared__ float hs[H];
    int xi = x[i];
    if (t < H) {
        float val = embed[(size_t)xi * H + t];
        hs[t] = val;
        d_h[i * H + t] = val;
    }
    __syncthreads();
    if (t < H) {
        float acc = 0.f;
        #pragma unroll 4
        for (int k = 0; k < H; k++)
            acc = fmaf(hs[k], ggc[k * H + t], acc);
        d_m[i * H + t]   = acc;
        d_agg[i * H + t] = 0.f;
    }
}

// ------------------------------------------------------------------
// K2: agg[dst] += w_e * m[src]    (atomic scatter over edges)
// ------------------------------------------------------------------
__global__ void k2_scatter(const int* __restrict__ ei,
                           const float* __restrict__ ew)
{
    int idx = blockIdx.x * blockDim.x + threadIdx.x;
    if (idx >= EDGES * H) return;
    int e = idx / H;
    int h = idx - e * H;
    int src = ei[e];
    int dst = ei[EDGES + e];
    atomicAdd(&d_agg[dst * H + h], ew[e] * d_m[src * H + h]);
}

// ------------------------------------------------------------------
// K3: GRU cell -> d_v
// ------------------------------------------------------------------
__global__ void k3_gru(const float* __restrict__ wih,
                       const float* __restrict__ whh,
                       const float* __restrict__ bih,
                       const float* __restrict__ bhh)
{
    int i = blockIdx.x;
    int c = threadIdx.x;
    __shared__ float ag[H], hh[H];
    if (c < H) { ag[c] = d_agg[i * H + c]; hh[c] = d_h[i * H + c]; }
    __syncthreads();
    if (c < H) {
        float ir = bih[c], iz = bih[H + c], in = bih[2 * H + c];
        float hr = bhh[c], hz = bhh[H + c], hn = bhh[2 * H + c];
        const float* wr = wih + (size_t)c * H;
        const float* wz = wih + (size_t)(H + c) * H;
        const float* wn = wih + (size_t)(2 * H + c) * H;
        const float* ur = whh + (size_t)c * H;
        const float* uz = whh + (size_t)(H + c) * H;
        const float* un = whh + (size_t)(2 * H + c) * H;
        #pragma unroll 4
        for (int k = 0; k < H; k++) {
            float a = ag[k], hv = hh[k];
            ir = fmaf(a, wr[k], ir);
            iz = fmaf(a, wz[k], iz);
            in = fmaf(a, wn[k], in);
            hr = fmaf(hv, ur[k], hr);
            hz = fmaf(hv, uz[k], hz);
            hn = fmaf(hv, un[k], hn);
        }
        float r  = 1.f / (1.f + __expf(-(ir + hr)));
        float zg = 1.f / (1.f + __expf(-(iz + hz)));
        float ng = tanhf(in + r * hn);
        d_v[i * H + c] = (1.f - zg) * ng + zg * hh[c];
    }
}

// ------------------------------------------------------------------
// K4: per-batch attention readout -> d_sh, and vt -> d_vt
// one block per batch, 128 threads
// ------------------------------------------------------------------
__global__ void k4_attn(const float* __restrict__ W1, const float* __restrict__ b1,
                        const float* __restrict__ W2, const float* __restrict__ b2,
                        const float* __restrict__ Wt, const float* __restrict__ bt,
                        const float* __restrict__ qw, const float* __restrict__ qb,
                        const float* __restrict__ W3, const float* __restrict__ b3)
{
    int b = blockIdx.x;
    int t = threadIdx.x;
    __shared__ float vs[LSEQ * H];
    __shared__ float w1s[H];
    __shared__ float as[LSEQ * H];
    __shared__ float alpha[LSEQ];
    __shared__ float sg[H];

    for (int idx = t; idx < LSEQ * H; idx += blockDim.x)
        vs[idx] = d_v[b * LSEQ * H + idx];
    __syncthreads();

    if (t < H) {                       // W1 @ s_l
        float acc = b1[t];
        const float* w = W1 + (size_t)t * H;
        for (int k = 0; k < H; k++) acc = fmaf(vs[(LSEQ - 1) * H + k], w[k], acc);
        w1s[t] = acc;
    }
    __syncthreads();

    if (t < H) {                       // a[l,h] = sigmoid(w1s + W2 v_l + b2)
        const float* w = W2 + (size_t)t * H;
        for (int l = 0; l < LSEQ; l++) {
            float acc = b2[t];
            for (int k = 0; k < H; k++) acc = fmaf(vs[l * H + k], w[k], acc);
            as[l * H + t] = 1.f / (1.f + __expf(-(w1s[t] + acc)));
        }
    }
    __syncthreads();

    if (t < LSEQ) {                    // alpha[l] = a[l] . q + qb
        float acc = qb[0];
        for (int k = 0; k < H; k++) acc = fmaf(as[t * H + k], qw[k], acc);
        alpha[t] = acc;
    }
    __syncthreads();

    if (t < H) {                       // s_g
        float acc = 0.f;
        for (int l = 0; l < LSEQ; l++) acc = fmaf(alpha[l], vs[l * H + t], acc);
        sg[t] = acc;
    }
    __syncthreads();

    if (t < H) {
        // s_h = [s_l, s_g] @ W3^T + b3
        float acc = b3[t];
        const float* w = W3 + (size_t)t * 2 * H;
        for (int k = 0; k < H; k++) acc = fmaf(vs[(LSEQ - 1) * H + k], w[k], acc);
        for (int k = 0; k < H; k++) acc = fmaf(sg[k], w[H + k], acc);
        d_sh[b * H + t] = acc;

        // vt[b,l,:] = v[b,l] @ Wt^T + bt
        const float* wt = Wt + (size_t)t * H;
        for (int l = 0; l < LSEQ; l++) {
            float a2 = bt[t];
            for (int k = 0; k < H; k++) a2 = fmaf(vs[l * H + k], wt[k], a2);
            d_vt[(b * LSEQ + l) * H + t] = a2;
        }
    }
}

// ------------------------------------------------------------------
// K5: the big fused kernel.
// z[b,j] = s_h[b].embed[j] + softmax_l(embed[j].vt[b,l]) . (embed[j].v[b,l])
// thread owns one j; embed row lives in 25x float4 registers;
// per-batch vt/v/sh staged in smem, read as broadcast LDS.128.
// ------------------------------------------------------------------
__global__ void __launch_bounds__(256, 1)
k5_main(const float* __restrict__ embed, float* __restrict__ out)
{
    __shared__ float4 svt[LSEQ * H4];
    __shared__ float4 sv [LSEQ * H4];
    __shared__ float4 ssh[H4];

    int t = threadIdx.x;
    int j = blockIdx.x * 256 + t;
    int jj = j < NNODE ? j : NNODE - 1;   // clamp: keeps warps convergent

    float4 e4[H4];
    const float4* eg = (const float4*)(embed + (size_t)jj * H);
    #pragma unroll
    for (int k = 0; k < H4; k++) e4[k] = eg[k];

    for (int b = 0; b < BATCH; b++) {
        __syncthreads();
        {
            float* svt_f = (float*)svt;
            float* sv_f  = (float*)sv;
            const float* gvt = d_vt + b * LSEQ * H;
            const float* gv  = d_v  + b * LSEQ * H;
            for (int idx = t; idx < LSEQ * H; idx += 256) {
                svt_f[idx] = gvt[idx];
                sv_f [idx] = gv [idx];
            }
            if (t < H) ((float*)ssh)[t] = d_sh[b * H + t];
        }
        __syncthreads();

        // P logits
        float p[LSEQ];
        #pragma unroll
        for (int l = 0; l < LSEQ; l++) {
            float4 acc = make_float4(0.f, 0.f, 0.f, 0.f);
            #pragma unroll
            for (int k = 0; k < H4; k++) {
                float4 w = svt[l * H4 + k];
                acc.x = fmaf(e4[k].x, w.x, acc.x);
                acc.y = fmaf(e4[k].y, w.y, acc.y);
                acc.z = fmaf(e4[k].z, w.z, acc.z);
                acc.w = fmaf(e4[k].w, w.w, acc.w);
            }
            p[l] = (acc.x + acc.y) + (acc.z + acc.w);
        }
        float mx = p[0];
        #pragma unroll
        for (int l = 1; l < LSEQ; l++) mx = fmaxf(mx, p[l]);

        // C + online softmax-weighted sum
        float esum = 0.f, wsum = 0.f;
        #pragma unroll
        for (int l = 0; l < LSEQ; l++) {
            float4 acc = make_float4(0.f, 0.f, 0.f, 0.f);
            #pragma unroll
            for (int k = 0; k < H4; k++) {
                float4 w = sv[l * H4 + k];
                acc.x = fmaf(e4[k].x, w.x, acc.x);
                acc.y = fmaf(e4[k].y, w.y, acc.y);
                acc.z = fmaf(e4[k].z, w.z, acc.z);
                acc.w = fmaf(e4[k].w, w.w, acc.w);
            }
            float cl = (acc.x + acc.y) + (acc.z + acc.w);
            float ex = __expf(p[l] - mx);
            esum += ex;
            wsum = fmaf(ex, cl, wsum);
        }

        // base = s_h . e
        float4 accb = make_float4(0.f, 0.f, 0.f, 0.f);
        #pragma unroll
        for (int k = 0; k < H4; k++) {
            float4 w = ssh[k];
            accb.x = fmaf(e4[k].x, w.x, accb.x);
            accb.y = fmaf(e4[k].y, w.y, accb.y);
            accb.z = fmaf(e4[k].z, w.z, accb.z);
            accb.w = fmaf(e4[k].w, w.w, accb.w);
        }
        float base = (accb.x + accb.y) + (accb.z + accb.w);

        if (j < NNODE)
            out[(size_t)b * NNODE + j] = base + wsum / esum;
    }
}

// ------------------------------------------------------------------
extern "C" void kernel_launch(void* const* d_in, const int* in_sizes, int n_in,
                              void* d_out, int out_size)
{
    const int*   x     = (const int*)  d_in[0];
    const int*   ei    = (const int*)  d_in[1];
    const float* ew    = (const float*)d_in[2];
    // d_in[3] = batch (unused; implied by arange//L)
    const float* embed = (const float*)d_in[4];
    const float* ggc   = (const float*)d_in[5];
    const float* wih   = (const float*)d_in[6];
    const float* whh   = (const float*)d_in[7];
    const float* bih   = (const float*)d_in[8];
    const float* bhh   = (const float*)d_in[9];
    const float* W1    = (const float*)d_in[10];
    const float* b1    = (const float*)d_in[11];
    const float* W2    = (const float*)d_in[12];
    const float* b2    = (const float*)d_in[13];
    const float* Wt    = (const float*)d_in[14];
    const float* bt    = (const float*)d_in[15];
    const float* qw    = (const float*)d_in[16];
    const float* qb    = (const float*)d_in[17];
    const float* W3    = (const float*)d_in[18];
    const float* b3    = (const float*)d_in[19];
    float* out = (float*)d_out;

    k1_gather_m<<<NNODES, 128>>>(x, embed, ggc);
    k2_scatter <<<(EDGES * H + 255) / 256, 256>>>(ei, ew);
    k3_gru     <<<NNODES, 128>>>(wih, whh, bih, bhh);
    k4_attn    <<<BATCH, 128>>>(W1, b1, W2, b2, Wt, bt, qw, qb, W3, b3);
    k5_main    <<<(NNODE + 255) / 256, 256>>>(embed, out);
}

// round 2
// speedup vs baseline: 1.2908x; 1.2908x over previous
#include <cuda_runtime.h>
#include <math.h>

#define H       100
#define NNODES  1024    // N = B*L
#define BATCH   64
#define LSEQ    16
#define EDGES   2048
#define NNODE   40000
#define H2      50      // H/2 packed f32x2 per row
#define H4      25      // H/4 16-byte vectors per row

#define JTILE   128     // j per CTA in k5
#define NJT     313     // ceil(40000/128)
#define BCHUNK  8       // batches per CTA in k5
#define NBC     (BATCH / BCHUNK)

// packed dual-FMA (SASS FFMA2) — only reachable via PTX
#define FMA2(d, a, b, c) \
    asm("fma.rn.f32x2 %0, %1, %2, %3;" : "=l"(d) : "l"(a), "l"(b), "l"(c))

__device__ __forceinline__ float sum2(unsigned long long v) {
    return __int_as_float((int)(v & 0xffffffffu)) + __int_as_float((int)(v >> 32));
}

// ---- scratch (no allocations allowed) ----
__device__ float d_h  [NNODES * H];
__device__ float d_m  [NNODES * H];   // m, then reused for W2-pre
__device__ float d_agg[NNODES * H];
__device__ float d_v  [NNODES * H];
__device__ float d_vt [NNODES * H];
__device__ float d_sh [BATCH  * H];

// ------------------------------------------------------------------
// K1: h = embed[x];  m = h @ ggc_w[0];  agg = 0
// ------------------------------------------------------------------
__global__ void k1_gather_m(const int* __restrict__ x,
                            const float* __restrict__ embed,
                            const float* __restrict__ ggc)
{
    int i = blockIdx.x;
    int t = threadIdx.x;
    __shared__ float hs[H];
    int xi = x[i];
    if (t < H) {
        float val = embed[(size_t)xi * H + t];
        hs[t] = val;
        d_h[i * H + t] = val;
    }
    __syncthreads();
    if (t < H) {
        float acc = 0.f;
        #pragma unroll 4
        for (int k = 0; k < H; k++)
            acc = fmaf(hs[k], ggc[k * H + t], acc);
        d_m[i * H + t]   = acc;
        d_agg[i * H + t] = 0.f;
    }
}

// ------------------------------------------------------------------
// K2: agg[dst] += w_e * m[src]
// ------------------------------------------------------------------
__global__ void k2_scatter(const int* __restrict__ ei,
                           const float* __restrict__ ew)
{
    int idx = blockIdx.x * blockDim.x + threadIdx.x;
    if (idx >= EDGES * H) return;
    int e = idx / H;
    int h = idx - e * H;
    int src = ei[e];
    int dst = ei[EDGES + e];
    atomicAdd(&d_agg[dst * H + h], ew[e] * d_m[src * H + h]);
}

// ------------------------------------------------------------------
// K3: GRU cell -> d_v, then (fused) W2-pre -> d_m, vt -> d_vt
// one block per node, 128 threads
// ------------------------------------------------------------------
__global__ void k3_gru_post(const float* __restrict__ wih,
                            const float* __restrict__ whh,
                            const float* __restrict__ bih,
                            const float* __restrict__ bhh,
                            const float* __restrict__ W2,
                            const float* __restrict__ b2,
                            const float* __restrict__ Wt,
                            const float* __restrict__ bt)
{
    int i = blockIdx.x;
    int c = threadIdx.x;
    __shared__ float ag[H], hh[H], vrow[H];
    if (c < H) { ag[c] = d_agg[i * H + c]; hh[c] = d_h[i * H + c]; }
    __syncthreads();
    if (c < H) {
        float ir = bih[c], iz = bih[H + c], in = bih[2 * H + c];
        float hr = bhh[c], hz = bhh[H + c], hn = bhh[2 * H + c];
        const float* wr = wih + (size_t)c * H;
        const float* wz = wih + (size_t)(H + c) * H;
        const float* wn = wih + (size_t)(2 * H + c) * H;
        const float* ur = whh + (size_t)c * H;
        const float* uz = whh + (size_t)(H + c) * H;
        const float* un = whh + (size_t)(2 * H + c) * H;
        #pragma unroll 4
        for (int k = 0; k < H; k++) {
            float a = ag[k], hv = hh[k];
            ir = fmaf(a, wr[k], ir);
            iz = fmaf(a, wz[k], iz);
            in = fmaf(a, wn[k], in);
            hr = fmaf(hv, ur[k], hr);
            hz = fmaf(hv, uz[k], hz);
            hn = fmaf(hv, un[k], hn);
        }
        float r  = 1.f / (1.f + __expf(-(ir + hr)));
        float zg = 1.f / (1.f + __expf(-(iz + hz)));
        float ng = tanhf(in + r * hn);
        float nv = (1.f - zg) * ng + zg * hh[c];
        vrow[c] = nv;
        d_v[i * H + c] = nv;
    }
    __syncthreads();
    if (c < H) {
        float a2 = b2[c], a3 = bt[c];
        const float* w2 = W2 + (size_t)c * H;
        const float* wt = Wt + (size_t)c * H;
        #pragma unroll 4
        for (int k = 0; k < H; k++) {
            float vv = vrow[k];
            a2 = fmaf(vv, w2[k], a2);
            a3 = fmaf(vv, wt[k], a3);
        }
        d_m [i * H + c] = a2;   // v @ W2^T + b2 (pre-sigmoid, w/o w1s)
        d_vt[i * H + c] = a3;   // v @ Wt^T + bt
    }
}

// ------------------------------------------------------------------
// K4: per-batch light reductions -> d_sh
// ------------------------------------------------------------------
__global__ void k4_attn(const float* __restrict__ W1, const float* __restrict__ b1,
                        const float* __restrict__ qw, const float* __restrict__ qb,
                        const float* __restrict__ W3, const float* __restrict__ b3)
{
    int b = blockIdx.x;
    int t = threadIdx.x;
    __shared__ float sl[H];
    __shared__ float w1s[H];
    __shared__ float as[LSEQ * H];
    __shared__ float alpha[LSEQ];
    __shared__ float sg[H];

    if (t < H) sl[t] = d_v[(b * LSEQ + LSEQ - 1) * H + t];
    __syncthreads();

    if (t < H) {                       // W1 @ s_l
        float acc = b1[t];
        const float* w = W1 + (size_t)t * H;
        for (int k = 0; k < H; k++) acc = fmaf(sl[k], w[k], acc);
        w1s[t] = acc;
    }
    __syncthreads();

    // as[l,h] = sigmoid(w1s + precomputed(W2 v_l + b2))
    for (int idx = t; idx < LSEQ * H; idx += blockDim.x) {
        int l = idx / H, hh2 = idx - l * H;
        float pre = d_m[(b * LSEQ + l) * H + hh2];
        as[idx] = 1.f / (1.f + __expf(-(w1s[hh2] + pre)));
    }
    __syncthreads();

    if (t < LSEQ) {
        float acc = qb[0];
        for (int k = 0; k < H; k++) acc = fmaf(as[t * H + k], qw[k], acc);
        alpha[t] = acc;
    }
    __syncthreads();

    if (t < H) {
        float acc = 0.f;
        for (int l = 0; l < LSEQ; l++) acc = fmaf(alpha[l], d_v[(b * LSEQ + l) * H + t], acc);
        sg[t] = acc;
    }
    __syncthreads();

    if (t < H) {
        float acc = b3[t];
        const float* w = W3 + (size_t)t * 2 * H;
        for (int k = 0; k < H; k++) acc = fmaf(sl[k], w[k], acc);
        for (int k = 0; k < H; k++) acc = fmaf(sg[k], w[H + k], acc);
        d_sh[b * H + t] = acc;
    }
}

// ------------------------------------------------------------------
// K5: fused output kernel, packed f32x2 math.
// z[b,j] = s_h[b].e_j + softmax_l(e_j.vt[b,l]) . (e_j.v[b,l])
// grid (NJT, NBC): blockIdx.x -> 128 j's, blockIdx.y -> 8 batches.
// ------------------------------------------------------------------
__global__ void __launch_bounds__(JTILE)
k5_main(const float* __restrict__ embed, float* __restrict__ out)
{
    __shared__ __align__(16) unsigned long long svt[LSEQ * H2];
    __shared__ __align__(16) unsigned long long sv [LSEQ * H2];
    __shared__ __align__(16) unsigned long long ssh[H2];

    int t = threadIdx.x;
    int j = blockIdx.x * JTILE + t;
    int jj = j < NNODE ? j : NNODE - 1;     // clamp: keeps warps convergent
    int b0 = blockIdx.y * BCHUNK;

    // embed row -> 50 packed f32x2 registers (25x LDG.128)
    unsigned long long e2[H2];
    {
        const ulonglong2* eg = (const ulonglong2*)(embed + (size_t)jj * H);
        #pragma unroll
        for (int k = 0; k < H4; k++) {
            ulonglong2 v = eg[k];
            e2[2 * k]     = v.x;
            e2[2 * k + 1] = v.y;
        }
    }

    for (int bc = 0; bc < BCHUNK; bc++) {
        int b = b0 + bc;
        __syncthreads();
        {
            float* svt_f = (float*)svt;
            float* sv_f  = (float*)sv;
            const float* gvt = d_vt + b * LSEQ * H;
            const float* gv  = d_v  + b * LSEQ * H;
            for (int idx = t; idx < LSEQ * H; idx += JTILE) {
                svt_f[idx] = gvt[idx];
                sv_f [idx] = gv [idx];
            }
            if (t < H) ((float*)ssh)[t] = d_sh[b * H + t];
        }
        __syncthreads();

        // P logits: p[l] = e . vt_l
        float p[LSEQ];
        #pragma unroll
        for (int l = 0; l < LSEQ; l++) {
            const ulonglong2* wrow = (const ulonglong2*)(svt + l * H2);
            unsigned long long a0 = 0ull, a1 = 0ull;
            #pragma unroll
            for (int k = 0; k < H4; k++) {
                ulonglong2 w = wrow[k];
                FMA2(a0, e2[2 * k],     w.x, a0);
                FMA2(a1, e2[2 * k + 1], w.y, a1);
            }
            p[l] = sum2(a0) + sum2(a1);
        }
        float mx = p[0];
        #pragma unroll
        for (int l = 1; l < LSEQ; l++) mx = fmaxf(mx, p[l]);

        // C + softmax-weighted sum
        float esum = 0.f, wsum = 0.f;
        #pragma unroll
        for (int l = 0; l < LSEQ; l++) {
            const ulonglong2* wrow = (const ulonglong2*)(sv + l * H2);
            unsigned long long a0 = 0ull, a1 = 0ull;
            #pragma unroll
            for (int k = 0; k < H4; k++) {
                ulonglong2 w = wrow[k];
                FMA2(a0, e2[2 * k],     w.x, a0);
                FMA2(a1, e2[2 * k + 1], w.y, a1);
            }
            float cl = sum2(a0) + sum2(a1);
            float ex = __expf(p[l] - mx);
            esum += ex;
            wsum = fmaf(ex, cl, wsum);
        }

        // base = s_h . e
        float base;
        {
            const ulonglong2* wrow = (const ulonglong2*)ssh;
            unsigned long long a0 = 0ull, a1 = 0ull;
            #pragma unroll
            for (int k = 0; k < H4; k++) {
                ulonglong2 w = wrow[k];
                FMA2(a0, e2[2 * k],     w.x, a0);
                FMA2(a1, e2[2 * k + 1], w.y, a1);
            }
            base = sum2(a0) + sum2(a1);
        }

        if (j < NNODE)
            out[(size_t)b * NNODE + j] = base + wsum / esum;
    }
}

// ------------------------------------------------------------------
extern "C" void kernel_launch(void* const* d_in, const int* in_sizes, int n_in,
                              void* d_out, int out_size)
{
    const int*   x     = (const int*)  d_in[0];
    const int*   ei    = (const int*)  d_in[1];
    const float* ew    = (const float*)d_in[2];
    // d_in[3] = batch (unused)
    const float* embed = (const float*)d_in[4];
    const float* ggc   = (const float*)d_in[5];
    const float* wih   = (const float*)d_in[6];
    const float* whh   = (const float*)d_in[7];
    const float* bih   = (const float*)d_in[8];
    const float* bhh   = (const float*)d_in[9];
    const float* W1    = (const float*)d_in[10];
    const float* b1    = (const float*)d_in[11];
    const float* W2    = (const float*)d_in[12];
    const float* b2    = (const float*)d_in[13];
    const float* Wt    = (const float*)d_in[14];
    const float* bt    = (const float*)d_in[15];
    const float* qw    = (const float*)d_in[16];
    const float* qb    = (const float*)d_in[17];
    const float* W3    = (const float*)d_in[18];
    const float* b3    = (const float*)d_in[19];
    float* out = (float*)d_out;

    k1_gather_m<<<NNODES, 128>>>(x, embed, ggc);
    k2_scatter <<<(EDGES * H + 255) / 256, 256>>>(ei, ew);
    k3_gru_post<<<NNODES, 128>>>(wih, whh, bih, bhh, W2, b2, Wt, bt);
    k4_attn    <<<BATCH, 128>>>(W1, b1, qw, qb, W3, b3);
    dim3 g5(NJT, NBC);
    k5_main    <<<g5, JTILE>>>(embed, out);
}

// round 3
// speedup vs baseline: 1.4727x; 1.1410x over previous
#include <cuda_runtime.h>
#include <math.h>

#define H       100
#define NNODES  1024    // N = B*L
#define BATCH   64
#define LSEQ    16
#define EDGES   2048
#define NNODE   40000
#define H2      50      // H/2 packed f32x2 per row
#define H4      25      // H/4 16-byte vectors per row

#define JTILE   128     // j per CTA in k5
#define NJT     313     // ceil(40000/128)
#define BCHUNK  8       // batches per CTA in k5
#define NBC     (BATCH / BCHUNK)
#define NPB     8       // nodes per block in k3

typedef unsigned long long ull;

// packed dual-FMA (SASS FFMA2) — only reachable via PTX
#define FMA2(d, a, b, c) \
    asm("fma.rn.f32x2 %0, %1, %2, %3;" : "=l"(d) : "l"(a), "l"(b), "l"(c))

__device__ __forceinline__ float sum2(ull v) {
    return __int_as_float((int)(v & 0xffffffffu)) + __int_as_float((int)(v >> 32));
}

// ---- scratch (no allocations allowed) ----
__device__ float d_h  [NNODES * H];
__device__ float d_m  [NNODES * H];   // m, then reused for W2-pre
__device__ float d_agg[NNODES * H];
__device__ float d_v  [NNODES * H];
__device__ float d_vt [NNODES * H];
__device__ float d_sh [BATCH  * H];

// ------------------------------------------------------------------
// K1: h = embed[x];  m = h @ ggc_w[0];  agg = 0
// ------------------------------------------------------------------
__global__ void k1_gather_m(const int* __restrict__ x,
                            const float* __restrict__ embed,
                            const float* __restrict__ ggc)
{
    int i = blockIdx.x;
    int t = threadIdx.x;
    __shared__ float hs[H];
    int xi = x[i];
    if (t < H) {
        float val = embed[(size_t)xi * H + t];
        hs[t] = val;
        d_h[i * H + t] = val;
    }
    __syncthreads();
    if (t < H) {
        float acc = 0.f;
        #pragma unroll 4
        for (int k = 0; k < H; k++)
            acc = fmaf(hs[k], ggc[k * H + t], acc);
        d_m[i * H + t]   = acc;
        d_agg[i * H + t] = 0.f;
    }
}

// ------------------------------------------------------------------
// K2: agg[dst] += w_e * m[src]
// ------------------------------------------------------------------
__global__ void k2_scatter(const int* __restrict__ ei,
                           const float* __restrict__ ew)
{
    int idx = blockIdx.x * blockDim.x + threadIdx.x;
    if (idx >= EDGES * H) return;
    int e = idx / H;
    int h = idx - e * H;
    int src = ei[e];
    int dst = ei[EDGES + e];
    atomicAdd(&d_agg[dst * H + h], ew[e] * d_m[src * H + h]);
}

// ------------------------------------------------------------------
// K3: GRU + fused W2-pre/vt. 8 nodes per block; weight rows loaded as
// float4 ONCE per thread and reused across all 8 nodes (coalescing fix).
// ------------------------------------------------------------------
__global__ void __launch_bounds__(128)
k3_gru_post(const float* __restrict__ wih,
            const float* __restrict__ whh,
            const float* __restrict__ bih,
            const float* __restrict__ bhh,
            const float* __restrict__ W2,
            const float* __restrict__ b2,
            const float* __restrict__ Wt,
            const float* __restrict__ bt)
{
    int node0 = blockIdx.x * NPB;
    int c = threadIdx.x;
    __shared__ __align__(16) float ag[NPB * H];
    __shared__ __align__(16) float hh[NPB * H];
    __shared__ __align__(16) float vv[NPB * H];

    for (int idx = c; idx < NPB * H; idx += 128) {
        ag[idx] = d_agg[node0 * H + idx];
        hh[idx] = d_h  [node0 * H + idx];
    }
    __syncthreads();

    if (c < H) {
        float air[NPB], aiz[NPB], ain[NPB], ahr[NPB], ahz[NPB], ahn[NPB];
        float br = bih[c], bz = bih[H + c], bn = bih[2 * H + c];
        float cr = bhh[c], cz = bhh[H + c], cn = bhh[2 * H + c];
        #pragma unroll
        for (int n = 0; n < NPB; n++) {
            air[n] = br; aiz[n] = bz; ain[n] = bn;
            ahr[n] = cr; ahz[n] = cz; ahn[n] = cn;
        }
        const float4* wr4 = (const float4*)(wih + (size_t)c * H);
        const float4* wz4 = (const float4*)(wih + (size_t)(H + c) * H);
        const float4* wn4 = (const float4*)(wih + (size_t)(2 * H + c) * H);
        const float4* ur4 = (const float4*)(whh + (size_t)c * H);
        const float4* uz4 = (const float4*)(whh + (size_t)(H + c) * H);
        const float4* un4 = (const float4*)(whh + (size_t)(2 * H + c) * H);

        for (int k = 0; k < H4; k++) {
            float4 wr = wr4[k], wz = wz4[k], wn = wn4[k];
            float4 ur = ur4[k], uz = uz4[k], un = un4[k];
            #pragma unroll
            for (int n = 0; n < NPB; n++) {
                float4 a  = *(const float4*)&ag[n * H + 4 * k];
                float4 hv = *(const float4*)&hh[n * H + 4 * k];
                air[n] = fmaf(a.x, wr.x, air[n]); air[n] = fmaf(a.y, wr.y, air[n]);
                air[n] = fmaf(a.z, wr.z, air[n]); air[n] = fmaf(a.w, wr.w, air[n]);
                aiz[n] = fmaf(a.x, wz.x, aiz[n]); aiz[n] = fmaf(a.y, wz.y, aiz[n]);
                aiz[n] = fmaf(a.z, wz.z, aiz[n]); aiz[n] = fmaf(a.w, wz.w, aiz[n]);
                ain[n] = fmaf(a.x, wn.x, ain[n]); ain[n] = fmaf(a.y, wn.y, ain[n]);
                ain[n] = fmaf(a.z, wn.z, ain[n]); ain[n] = fmaf(a.w, wn.w, ain[n]);
                ahr[n] = fmaf(hv.x, ur.x, ahr[n]); ahr[n] = fmaf(hv.y, ur.y, ahr[n]);
                ahr[n] = fmaf(hv.z, ur.z, ahr[n]); ahr[n] = fmaf(hv.w, ur.w, ahr[n]);
                ahz[n] = fmaf(hv.x, uz.x, ahz[n]); ahz[n] = fmaf(hv.y, uz.y, ahz[n]);
                ahz[n] = fmaf(hv.z, uz.z, ahz[n]); ahz[n] = fmaf(hv.w, uz.w, ahz[n]);
                ahn[n] = fmaf(hv.x, un.x, ahn[n]); ahn[n] = fmaf(hv.y, un.y, ahn[n]);
                ahn[n] = fmaf(hv.z, un.z, ahn[n]); ahn[n] = fmaf(hv.w, un.w, ahn[n]);
            }
        }
        #pragma unroll
        for (int n = 0; n < NPB; n++) {
            float r  = 1.f / (1.f + __expf(-(air[n] + ahr[n])));
            float zg = 1.f / (1.f + __expf(-(aiz[n] + ahz[n])));
            float ng = tanhf(ain[n] + r * ahn[n]);
            float nv = (1.f - zg) * ng + zg * hh[n * H + c];
            vv[n * H + c] = nv;
            d_v[(node0 + n) * H + c] = nv;
        }
    }
    __syncthreads();

    if (c < H) {
        float a2[NPB], a3[NPB];
        float bb2 = b2[c], bbt = bt[c];
        #pragma unroll
        for (int n = 0; n < NPB; n++) { a2[n] = bb2; a3[n] = bbt; }
        const float4* w2r = (const float4*)(W2 + (size_t)c * H);
        const float4* wtr = (const float4*)(Wt + (size_t)c * H);
        for (int k = 0; k < H4; k++) {
            float4 w2 = w2r[k], wt = wtr[k];
            #pragma unroll
            for (int n = 0; n < NPB; n++) {
                float4 v = *(const float4*)&vv[n * H + 4 * k];
                a2[n] = fmaf(v.x, w2.x, a2[n]); a2[n] = fmaf(v.y, w2.y, a2[n]);
                a2[n] = fmaf(v.z, w2.z, a2[n]); a2[n] = fmaf(v.w, w2.w, a2[n]);
                a3[n] = fmaf(v.x, wt.x, a3[n]); a3[n] = fmaf(v.y, wt.y, a3[n]);
                a3[n] = fmaf(v.z, wt.z, a3[n]); a3[n] = fmaf(v.w, wt.w, a3[n]);
            }
        }
        #pragma unroll
        for (int n = 0; n < NPB; n++) {
            d_m [(node0 + n) * H + c] = a2[n];   // v @ W2^T + b2 (pre-sigmoid)
            d_vt[(node0 + n) * H + c] = a3[n];   // v @ Wt^T + bt
        }
    }
}

// ------------------------------------------------------------------
// K4: per-batch light reductions -> d_sh
// ------------------------------------------------------------------
__global__ void k4_attn(const float* __restrict__ W1, const float* __restrict__ b1,
                        const float* __restrict__ qw, const float* __restrict__ qb,
                        const float* __restrict__ W3, const float* __restrict__ b3)
{
    int b = blockIdx.x;
    int t = threadIdx.x;
    __shared__ __align__(16) float sl[H];
    __shared__ float w1s[H];
    __shared__ float as[LSEQ * H];
    __shared__ float alpha[LSEQ];
    __shared__ __align__(16) float sg[H];

    if (t < H) sl[t] = d_v[(b * LSEQ + LSEQ - 1) * H + t];
    __syncthreads();

    if (t < H) {                       // W1 @ s_l
        float acc = b1[t];
        const float4* w = (const float4*)(W1 + (size_t)t * H);
        for (int k = 0; k < H4; k++) {
            float4 wv = w[k];
            float4 s = *(const float4*)&sl[4 * k];
            acc = fmaf(s.x, wv.x, acc); acc = fmaf(s.y, wv.y, acc);
            acc = fmaf(s.z, wv.z, acc); acc = fmaf(s.w, wv.w, acc);
        }
        w1s[t] = acc;
    }
    __syncthreads();

    for (int idx = t; idx < LSEQ * H; idx += blockDim.x) {
        int l = idx / H, hh2 = idx - l * H;
        float pre = d_m[(b * LSEQ + l) * H + hh2];
        as[idx] = 1.f / (1.f + __expf(-(w1s[hh2] + pre)));
    }
    __syncthreads();

    if (t < LSEQ) {
        float acc = qb[0];
        for (int k = 0; k < H; k++) acc = fmaf(as[t * H + k], qw[k], acc);
        alpha[t] = acc;
    }
    __syncthreads();

    if (t < H) {
        float acc = 0.f;
        for (int l = 0; l < LSEQ; l++) acc = fmaf(alpha[l], d_v[(b * LSEQ + l) * H + t], acc);
        sg[t] = acc;
    }
    __syncthreads();

    if (t < H) {
        float acc = b3[t];
        const float4* w  = (const float4*)(W3 + (size_t)t * 2 * H);
        for (int k = 0; k < H4; k++) {
            float4 wv = w[k];
            float4 s = *(const float4*)&sl[4 * k];
            acc = fmaf(s.x, wv.x, acc); acc = fmaf(s.y, wv.y, acc);
            acc = fmaf(s.z, wv.z, acc); acc = fmaf(s.w, wv.w, acc);
        }
        for (int k = 0; k < H4; k++) {
            float4 wv = w[H4 + k];
            float4 s = *(const float4*)&sg[4 * k];
            acc = fmaf(s.x, wv.x, acc); acc = fmaf(s.y, wv.y, acc);
            acc = fmaf(s.z, wv.z, acc); acc = fmaf(s.w, wv.w, acc);
        }
        d_sh[b * H + t] = acc;
    }
}

// ------------------------------------------------------------------
// K5: fused output kernel. l processed in groups of 4 -> 8 independent
// FFMA2 chains; per-k prefetch double-buffers the broadcast LDS.128.
// z[b,j] = s_h[b].e_j + softmax_l(e_j.vt[b,l]) . (e_j.v[b,l])
// ------------------------------------------------------------------
__global__ void __launch_bounds__(JTILE)
k5_main(const float* __restrict__ embed, float* __restrict__ out)
{
    __shared__ __align__(16) ull svt[LSEQ * H2];
    __shared__ __align__(16) ull sv [LSEQ * H2];
    __shared__ __align__(16) ull ssh[H2];

    int t = threadIdx.x;
    int j = blockIdx.x * JTILE + t;
    int jj = j < NNODE ? j : NNODE - 1;     // clamp: keeps warps convergent
    int b0 = blockIdx.y * BCHUNK;

    // embed row -> 50 packed f32x2 registers
    ull e2[H2];
    {
        const ulonglong2* eg = (const ulonglong2*)(embed + (size_t)jj * H);
        #pragma unroll
        for (int k = 0; k < H4; k++) {
            ulonglong2 v = eg[k];
            e2[2 * k]     = v.x;
            e2[2 * k + 1] = v.y;
        }
    }

    for (int bc = 0; bc < BCHUNK; bc++) {
        int b = b0 + bc;
        __syncthreads();
        {
            float4* svt4 = (float4*)svt;
            float4* sv4  = (float4*)sv;
            const float4* gvt = (const float4*)(d_vt + b * LSEQ * H);
            const float4* gv  = (const float4*)(d_v  + b * LSEQ * H);
            for (int idx = t; idx < LSEQ * H4; idx += JTILE) {
                svt4[idx] = gvt[idx];
                sv4 [idx] = gv [idx];
            }
            if (t < H4) ((float4*)ssh)[t] = ((const float4*)(d_sh + b * H))[t];
        }
        __syncthreads();

        // ---- P logits ----
        float p[LSEQ];
        #pragma unroll
        for (int lg = 0; lg < LSEQ / 4; lg++) {
            ull a0[4], a1[4];
            const ulonglong2* w[4];
            ulonglong2 cur[4];
            #pragma unroll
            for (int i = 0; i < 4; i++) {
                w[i] = (const ulonglong2*)(svt + (lg * 4 + i) * H2);
                cur[i] = w[i][0];
                a0[i] = 0ull; a1[i] = 0ull;
            }
            #pragma unroll
            for (int k = 0; k < H4; k++) {
                ulonglong2 nxt[4];
                if (k + 1 < H4) {
                    #pragma unroll
                    for (int i = 0; i < 4; i++) nxt[i] = w[i][k + 1];
                }
                ull ea = e2[2 * k], eb = e2[2 * k + 1];
                #pragma unroll
                for (int i = 0; i < 4; i++) {
                    FMA2(a0[i], ea, cur[i].x, a0[i]);
                    FMA2(a1[i], eb, cur[i].y, a1[i]);
                }
                if (k + 1 < H4) {
                    #pragma unroll
                    for (int i = 0; i < 4; i++) cur[i] = nxt[i];
                }
            }
            #pragma unroll
            for (int i = 0; i < 4; i++)
                p[lg * 4 + i] = sum2(a0[i]) + sum2(a1[i]);
        }
        float mx = p[0];
        #pragma unroll
        for (int l = 1; l < LSEQ; l++) mx = fmaxf(mx, p[l]);

        // ---- C + softmax-weighted sum ----
        float esum = 0.f, wsum = 0.f;
        #pragma unroll
        for (int lg = 0; lg < LSEQ / 4; lg++) {
            ull a0[4], a1[4];
            const ulonglong2* w[4];
            ulonglong2 cur[4];
            #pragma unroll
            for (int i = 0; i < 4; i++) {
                w[i] = (const ulonglong2*)(sv + (lg * 4 + i) * H2);
                cur[i] = w[i][0];
                a0[i] = 0ull; a1[i] = 0ull;
            }
            #pragma unroll
            for (int k = 0; k < H4; k++) {
                ulonglong2 nxt[4];
                if (k + 1 < H4) {
                    #pragma unroll
                    for (int i = 0; i < 4; i++) nxt[i] = w[i][k + 1];
                }
                ull ea = e2[2 * k], eb = e2[2 * k + 1];
                #pragma unroll
                for (int i = 0; i < 4; i++) {
                    FMA2(a0[i], ea, cur[i].x, a0[i]);
                    FMA2(a1[i], eb, cur[i].y, a1[i]);
                }
                if (k + 1 < H4) {
                    #pragma unroll
                    for (int i = 0; i < 4; i++) cur[i] = nxt[i];
                }
            }
            #pragma unroll
            for (int i = 0; i < 4; i++) {
                float cl = sum2(a0[i]) + sum2(a1[i]);
                float ex = __expf(p[lg * 4 + i] - mx);
                esum += ex;
                wsum = fmaf(ex, cl, wsum);
            }
        }

        // ---- base = s_h . e ----
        float base;
        {
            const ulonglong2* wrow = (const ulonglong2*)ssh;
            ull a0 = 0ull, a1 = 0ull;
            #pragma unroll
            for (int k = 0; k < H4; k++) {
                ulonglong2 w = wrow[k];
                FMA2(a0, e2[2 * k],     w.x, a0);
                FMA2(a1, e2[2 * k + 1], w.y, a1);
            }
            base = sum2(a0) + sum2(a1);
        }

        if (j < NNODE)
            out[(size_t)b * NNODE + j] = base + wsum / esum;
    }
}

// ------------------------------------------------------------------
extern "C" void kernel_launch(void* const* d_in, const int* in_sizes, int n_in,
                              void* d_out, int out_size)
{
    const int*   x     = (const int*)  d_in[0];
    const int*   ei    = (const int*)  d_in[1];
    const float* ew    = (const float*)d_in[2];
    // d_in[3] = batch (unused)
    const float* embed = (const float*)d_in[4];
    const float* ggc   = (const float*)d_in[5];
    const float* wih   = (const float*)d_in[6];
    const float* whh   = (const float*)d_in[7];
    const float* bih   = (const float*)d_in[8];
    const float* bhh   = (const float*)d_in[9];
    const float* W1    = (const float*)d_in[10];
    const float* b1    = (const float*)d_in[11];
    const float* W2    = (const float*)d_in[12];
    const float* b2    = (const float*)d_in[13];
    const float* Wt    = (const float*)d_in[14];
    const float* bt    = (const float*)d_in[15];
    const float* qw    = (const float*)d_in[16];
    const float* qb    = (const float*)d_in[17];
    const float* W3    = (const float*)d_in[18];
    const float* b3    = (const float*)d_in[19];
    float* out = (float*)d_out;

    k1_gather_m<<<NNODES, 128>>>(x, embed, ggc);
    k2_scatter <<<(EDGES * H + 255) / 256, 256>>>(ei, ew);
    k3_gru_post<<<NNODES / NPB, 128>>>(wih, whh, bih, bhh, W2, b2, Wt, bt);
    k4_attn    <<<BATCH, 128>>>(W1, b1, qw, qb, W3, b3);
    dim3 g5(NJT, NBC);
    k5_main    <<<g5, JTILE>>>(embed, out);
}

// round 4
// speedup vs baseline: 1.7565x; 1.1927x over previous
#include <cuda_runtime.h>
#include <math.h>

#define H       100
#define NNODES  1024    // N = B*L
#define BATCH   64
#define LSEQ    16
#define EDGES   2048
#define NNODE   40000
#define H4      25      // H/4 16-byte vectors per row

#define JTILE   128     // j per CTA in k5
#define NJT     313     // ceil(40000/128)
#define BCHUNK  8       // batches per CTA in k5
#define NBC     (BATCH / BCHUNK)
#define NPB     8       // nodes per block in k3
#define KCH     5       // k-chunks in k5 (20 floats each)

typedef unsigned long long ull;

// packed dual-FMA (SASS FFMA2) — only reachable via PTX
#define FMA2(d, a, b, c) \
    asm("fma.rn.f32x2 %0, %1, %2, %3;" : "=l"(d) : "l"(a), "l"(b), "l"(c))

__device__ __forceinline__ float sum2(ull v) {
    return __int_as_float((int)(v & 0xffffffffu)) + __int_as_float((int)(v >> 32));
}

// ---- scratch (no allocations allowed) ----
__device__ float d_h  [NNODES * H];
__device__ float d_m  [NNODES * H];   // m, then reused for W2-pre
__device__ float d_agg[NNODES * H];
__device__ float d_v  [NNODES * H];
__device__ float d_vt [NNODES * H];
__device__ float d_sh [BATCH  * H];

// ------------------------------------------------------------------
// K1: h = embed[x];  m = h @ ggc_w[0];  agg = 0
// ------------------------------------------------------------------
__global__ void k1_gather_m(const int* __restrict__ x,
                            const float* __restrict__ embed,
                            const float* __restrict__ ggc)
{
    int i = blockIdx.x;
    int t = threadIdx.x;
    __shared__ float hs[H];
    int xi = x[i];
    if (t < H) {
        float val = embed[(size_t)xi * H + t];
        hs[t] = val;
        d_h[i * H + t] = val;
    }
    __syncthreads();
    if (t < H) {
        float acc = 0.f;
        #pragma unroll 4
        for (int k = 0; k < H; k++)
            acc = fmaf(hs[k], ggc[k * H + t], acc);
        d_m[i * H + t]   = acc;
        d_agg[i * H + t] = 0.f;
    }
}

// ------------------------------------------------------------------
// K2: agg[dst] += w_e * m[src]
// ------------------------------------------------------------------
__global__ void k2_scatter(const int* __restrict__ ei,
                           const float* __restrict__ ew)
{
    int idx = blockIdx.x * blockDim.x + threadIdx.x;
    if (idx >= EDGES * H) return;
    int e = idx / H;
    int h = idx - e * H;
    int src = ei[e];
    int dst = ei[EDGES + e];
    atomicAdd(&d_agg[dst * H + h], ew[e] * d_m[src * H + h]);
}

// ------------------------------------------------------------------
// K3: GRU + fused W2-pre/vt. 8 nodes per block; weight rows loaded as
// float4 ONCE per thread and reused across all 8 nodes.
// ------------------------------------------------------------------
__global__ void __launch_bounds__(128)
k3_gru_post(const float* __restrict__ wih,
            const float* __restrict__ whh,
            const float* __restrict__ bih,
            const float* __restrict__ bhh,
            const float* __restrict__ W2,
            const float* __restrict__ b2,
            const float* __restrict__ Wt,
            const float* __restrict__ bt)
{
    int node0 = blockIdx.x * NPB;
    int c = threadIdx.x;
    __shared__ __align__(16) float ag[NPB * H];
    __shared__ __align__(16) float hh[NPB * H];
    __shared__ __align__(16) float vv[NPB * H];

    for (int idx = c; idx < NPB * H; idx += 128) {
        ag[idx] = d_agg[node0 * H + idx];
        hh[idx] = d_h  [node0 * H + idx];
    }
    __syncthreads();

    if (c < H) {
        float air[NPB], aiz[NPB], ain[NPB], ahr[NPB], ahz[NPB], ahn[NPB];
        float br = bih[c], bz = bih[H + c], bn = bih[2 * H + c];
        float cr = bhh[c], cz = bhh[H + c], cn = bhh[2 * H + c];
        #pragma unroll
        for (int n = 0; n < NPB; n++) {
            air[n] = br; aiz[n] = bz; ain[n] = bn;
            ahr[n] = cr; ahz[n] = cz; ahn[n] = cn;
        }
        const float4* wr4 = (const float4*)(wih + (size_t)c * H);
        const float4* wz4 = (const float4*)(wih + (size_t)(H + c) * H);
        const float4* wn4 = (const float4*)(wih + (size_t)(2 * H + c) * H);
        const float4* ur4 = (const float4*)(whh + (size_t)c * H);
        const float4* uz4 = (const float4*)(whh + (size_t)(H + c) * H);
        const float4* un4 = (const float4*)(whh + (size_t)(2 * H + c) * H);

        for (int k = 0; k < H4; k++) {
            float4 wr = wr4[k], wz = wz4[k], wn = wn4[k];
            float4 ur = ur4[k], uz = uz4[k], un = un4[k];
            #pragma unroll
            for (int n = 0; n < NPB; n++) {
                float4 a  = *(const float4*)&ag[n * H + 4 * k];
                float4 hv = *(const float4*)&hh[n * H + 4 * k];
                air[n] = fmaf(a.x, wr.x, air[n]); air[n] = fmaf(a.y, wr.y, air[n]);
                air[n] = fmaf(a.z, wr.z, air[n]); air[n] = fmaf(a.w, wr.w, air[n]);
                aiz[n] = fmaf(a.x, wz.x, aiz[n]); aiz[n] = fmaf(a.y, wz.y, aiz[n]);
                aiz[n] = fmaf(a.z, wz.z, aiz[n]); aiz[n] = fmaf(a.w, wz.w, aiz[n]);
                ain[n] = fmaf(a.x, wn.x, ain[n]); ain[n] = fmaf(a.y, wn.y, ain[n]);
                ain[n] = fmaf(a.z, wn.z, ain[n]); ain[n] = fmaf(a.w, wn.w, ain[n]);
                ahr[n] = fmaf(hv.x, ur.x, ahr[n]); ahr[n] = fmaf(hv.y, ur.y, ahr[n]);
                ahr[n] = fmaf(hv.z, ur.z, ahr[n]); ahr[n] = fmaf(hv.w, ur.w, ahr[n]);
                ahz[n] = fmaf(hv.x, uz.x, ahz[n]); ahz[n] = fmaf(hv.y, uz.y, ahz[n]);
                ahz[n] = fmaf(hv.z, uz.z, ahz[n]); ahz[n] = fmaf(hv.w, uz.w, ahz[n]);
                ahn[n] = fmaf(hv.x, un.x, ahn[n]); ahn[n] = fmaf(hv.y, un.y, ahn[n]);
                ahn[n] = fmaf(hv.z, un.z, ahn[n]); ahn[n] = fmaf(hv.w, un.w, ahn[n]);
            }
        }
        #pragma unroll
        for (int n = 0; n < NPB; n++) {
            float r  = 1.f / (1.f + __expf(-(air[n] + ahr[n])));
            float zg = 1.f / (1.f + __expf(-(aiz[n] + ahz[n])));
            float ng = tanhf(ain[n] + r * ahn[n]);
            float nv = (1.f - zg) * ng + zg * hh[n * H + c];
            vv[n * H + c] = nv;
            d_v[(node0 + n) * H + c] = nv;
        }
    }
    __syncthreads();

    if (c < H) {
        float a2[NPB], a3[NPB];
        float bb2 = b2[c], bbt = bt[c];
        #pragma unroll
        for (int n = 0; n < NPB; n++) { a2[n] = bb2; a3[n] = bbt; }
        const float4* w2r = (const float4*)(W2 + (size_t)c * H);
        const float4* wtr = (const float4*)(Wt + (size_t)c * H);
        for (int k = 0; k < H4; k++) {
            float4 w2 = w2r[k], wt = wtr[k];
            #pragma unroll
            for (int n = 0; n < NPB; n++) {
                float4 v = *(const float4*)&vv[n * H + 4 * k];
                a2[n] = fmaf(v.x, w2.x, a2[n]); a2[n] = fmaf(v.y, w2.y, a2[n]);
                a2[n] = fmaf(v.z, w2.z, a2[n]); a2[n] = fmaf(v.w, w2.w, a2[n]);
                a3[n] = fmaf(v.x, wt.x, a3[n]); a3[n] = fmaf(v.y, wt.y, a3[n]);
                a3[n] = fmaf(v.z, wt.z, a3[n]); a3[n] = fmaf(v.w, wt.w, a3[n]);
            }
        }
        #pragma unroll
        for (int n = 0; n < NPB; n++) {
            d_m [(node0 + n) * H + c] = a2[n];
            d_vt[(node0 + n) * H + c] = a3[n];
        }
    }
}

// ------------------------------------------------------------------
// K4: per-batch light reductions -> d_sh
// ------------------------------------------------------------------
__global__ void k4_attn(const float* __restrict__ W1, const float* __restrict__ b1,
                        const float* __restrict__ qw, const float* __restrict__ qb,
                        const float* __restrict__ W3, const float* __restrict__ b3)
{
    int b = blockIdx.x;
    int t = threadIdx.x;
    __shared__ __align__(16) float sl[H];
    __shared__ float w1s[H];
    __shared__ float as[LSEQ * H];
    __shared__ float alpha[LSEQ];
    __shared__ __align__(16) float sg[H];

    if (t < H) sl[t] = d_v[(b * LSEQ + LSEQ - 1) * H + t];
    __syncthreads();

    if (t < H) {
        float acc = b1[t];
        const float4* w = (const float4*)(W1 + (size_t)t * H);
        for (int k = 0; k < H4; k++) {
            float4 wv = w[k];
            float4 s = *(const float4*)&sl[4 * k];
            acc = fmaf(s.x, wv.x, acc); acc = fmaf(s.y, wv.y, acc);
            acc = fmaf(s.z, wv.z, acc); acc = fmaf(s.w, wv.w, acc);
        }
        w1s[t] = acc;
    }
    __syncthreads();

    for (int idx = t; idx < LSEQ * H; idx += blockDim.x) {
        int l = idx / H, hh2 = idx - l * H;
        float pre = d_m[(b * LSEQ + l) * H + hh2];
        as[idx] = 1.f / (1.f + __expf(-(w1s[hh2] + pre)));
    }
    __syncthreads();

    if (t < LSEQ) {
        float acc = qb[0];
        for (int k = 0; k < H; k++) acc = fmaf(as[t * H + k], qw[k], acc);
        alpha[t] = acc;
    }
    __syncthreads();

    if (t < H) {
        float acc = 0.f;
        for (int l = 0; l < LSEQ; l++) acc = fmaf(alpha[l], d_v[(b * LSEQ + l) * H + t], acc);
        sg[t] = acc;
    }
    __syncthreads();

    if (t < H) {
        float acc = b3[t];
        const float4* w  = (const float4*)(W3 + (size_t)t * 2 * H);
        for (int k = 0; k < H4; k++) {
            float4 wv = w[k];
            float4 s = *(const float4*)&sl[4 * k];
            acc = fmaf(s.x, wv.x, acc); acc = fmaf(s.y, wv.y, acc);
            acc = fmaf(s.z, wv.z, acc); acc = fmaf(s.w, wv.w, acc);
        }
        for (int k = 0; k < H4; k++) {
            float4 wv = w[H4 + k];
            float4 s = *(const float4*)&sg[4 * k];
            acc = fmaf(s.x, wv.x, acc); acc = fmaf(s.y, wv.y, acc);
            acc = fmaf(s.z, wv.z, acc); acc = fmaf(s.w, wv.w, acc);
        }
        d_sh[b * H + t] = acc;
    }
}

// ------------------------------------------------------------------
// K5: fused output. Single k-sweep accumulating all 33 dots at once:
// 16 P-logits + 16 C + base, in packed f32x2 accumulators (33 chains
// of ILP). Embed row held only as a 20-float register chunk, reloaded
// from L1 per chunk -> ~115 regs -> 4 warps/SMSP.
// ------------------------------------------------------------------
__global__ void __launch_bounds__(JTILE, 4)
k5_main(const float* __restrict__ embed, float* __restrict__ out)
{
    __shared__ __align__(16) float s_vt[LSEQ * H];
    __shared__ __align__(16) float s_v [LSEQ * H];
    __shared__ __align__(16) float s_sh[H + 4];

    int t = threadIdx.x;
    int j = blockIdx.x * JTILE + t;
    int jj = j < NNODE ? j : NNODE - 1;     // clamp: keeps warps convergent
    int b0 = blockIdx.y * BCHUNK;

    const float* erow = embed + (size_t)jj * H;

    #pragma unroll 1
    for (int bc = 0; bc < BCHUNK; bc++) {
        int b = b0 + bc;
        __syncthreads();
        {
            float4* svt4 = (float4*)s_vt;
            float4* sv4  = (float4*)s_v;
            const float4* gvt = (const float4*)(d_vt + b * LSEQ * H);
            const float4* gv  = (const float4*)(d_v  + b * LSEQ * H);
            #pragma unroll 1
            for (int idx = t; idx < LSEQ * H4; idx += JTILE) {
                svt4[idx] = gvt[idx];
                sv4 [idx] = gv [idx];
            }
            if (t < H4) ((float4*)s_sh)[t] = ((const float4*)(d_sh + b * H))[t];
        }
        __syncthreads();

        ull accP[LSEQ], accC[LSEQ], accS = 0ull;
        #pragma unroll
        for (int l = 0; l < LSEQ; l++) { accP[l] = 0ull; accC[l] = 0ull; }

        #pragma unroll 1
        for (int ch = 0; ch < KCH; ch++) {
            // load 20-float embed chunk (5x LDG.128, L1-resident)
            ull e[10];
            {
                const ulonglong2* eg = (const ulonglong2*)(erow + ch * 20);
                #pragma unroll
                for (int i = 0; i < 5; i++) {
                    ulonglong2 v = eg[i];
                    e[2 * i]     = v.x;
                    e[2 * i + 1] = v.y;
                }
            }
            #pragma unroll
            for (int l = 0; l < LSEQ; l++) {
                const ulonglong2* wp = (const ulonglong2*)(s_vt + l * H + ch * 20);
                const ulonglong2* wc = (const ulonglong2*)(s_v  + l * H + ch * 20);
                #pragma unroll
                for (int i = 0; i < 5; i++) {
                    ulonglong2 a = wp[i];
                    FMA2(accP[l], e[2 * i],     a.x, accP[l]);
                    FMA2(accP[l], e[2 * i + 1], a.y, accP[l]);
                    ulonglong2 c = wc[i];
                    FMA2(accC[l], e[2 * i],     c.x, accC[l]);
                    FMA2(accC[l], e[2 * i + 1], c.y, accC[l]);
                }
            }
            {
                const ulonglong2* ws = (const ulonglong2*)(s_sh + ch * 20);
                #pragma unroll
                for (int i = 0; i < 5; i++) {
                    ulonglong2 sd = ws[i];
                    FMA2(accS, e[2 * i],     sd.x, accS);
                    FMA2(accS, e[2 * i + 1], sd.y, accS);
                }
            }
        }

        // epilogue: softmax over l, weighted sum, base
        float p[LSEQ];
        #pragma unroll
        for (int l = 0; l < LSEQ; l++) p[l] = sum2(accP[l]);
        float mx = p[0];
        #pragma unroll
        for (int l = 1; l < LSEQ; l++) mx = fmaxf(mx, p[l]);
        float esum = 0.f, wsum = 0.f;
        #pragma unroll
        for (int l = 0; l < LSEQ; l++) {
            float ex = __expf(p[l] - mx);
            esum += ex;
            wsum = fmaf(ex, sum2(accC[l]), wsum);
        }
        float base = sum2(accS);

        if (j < NNODE)
            out[(size_t)b * NNODE + j] = base + wsum / esum;
    }
}

// ------------------------------------------------------------------
extern "C" void kernel_launch(void* const* d_in, const int* in_sizes, int n_in,
                              void* d_out, int out_size)
{
    const int*   x     = (const int*)  d_in[0];
    const int*   ei    = (const int*)  d_in[1];
    const float* ew    = (const float*)d_in[2];
    // d_in[3] = batch (unused)
    const float* embed = (const float*)d_in[4];
    const float* ggc   = (const float*)d_in[5];
    const float* wih   = (const float*)d_in[6];
    const float* whh   = (const float*)d_in[7];
    const float* bih   = (const float*)d_in[8];
    const float* bhh   = (const float*)d_in[9];
    const float* W1    = (const float*)d_in[10];
    const float* b1    = (const float*)d_in[11];
    const float* W2    = (const float*)d_in[12];
    const float* b2    = (const float*)d_in[13];
    const float* Wt    = (const float*)d_in[14];
    const float* bt    = (const float*)d_in[15];
    const float* qw    = (const float*)d_in[16];
    const float* qb    = (const float*)d_in[17];
    const float* W3    = (const float*)d_in[18];
    const float* b3    = (const float*)d_in[19];
    float* out = (float*)d_out;

    k1_gather_m<<<NNODES, 128>>>(x, embed, ggc);
    k2_scatter <<<(EDGES * H + 255) / 256, 256>>>(ei, ew);
    k3_gru_post<<<NNODES / NPB, 128>>>(wih, whh, bih, bhh, W2, b2, Wt, bt);
    k4_attn    <<<BATCH, 128>>>(W1, b1, qw, qb, W3, b3);
    dim3 g5(NJT, NBC);
    k5_main    <<<g5, JTILE>>>(embed, out);
}

// round 6
// speedup vs baseline: 3.9791x; 2.2654x over previous
#include <cuda_runtime.h>
#include <cuda_bf16.h>
#include <math.h>
#include <cstdint>

#define H       100
#define NNODES  1024    // N = B*L
#define BATCH   64
#define LSEQ    16
#define EDGES   2048
#define NNODE   40000
#define H4      25
#define NPB     8       // nodes per block in k3

// ---- mma.sync GEMM config ----
#define MT      128                // j rows per CTA (8 warps x m16)
#define NTILES  313                // ceil(40000/128)
#define JPAD    (NTILES * MT)      // 40064
#define KP      112                // padded K for embed (7 k-steps of 16)
#define KSTEPS  7
#define BROWS   40                 // B rows: 16 vt | 16 v | sh | 7 zero
#define BSTRIDE 120                // B row stride in bf16 (bank-conflict-free)
#define NTL     5                  // n8 tiles: 4 data + 1 base

typedef unsigned long long ull;

#define MMA16816(d, a, b0, b1)                                              \
    asm volatile("mma.sync.aligned.m16n8k16.row.col.f32.bf16.bf16.f32 "     \
        "{%0,%1,%2,%3}, {%4,%5,%6,%7}, {%8,%9}, {%0,%1,%2,%3};"             \
        : "+f"((d)[0]), "+f"((d)[1]), "+f"((d)[2]), "+f"((d)[3])            \
        : "r"((a)[0]), "r"((a)[1]), "r"((a)[2]), "r"((a)[3]),               \
          "r"(b0), "r"(b1))

// ---- scratch (no allocations allowed) ----
__device__ float d_h  [NNODES * H];
__device__ float d_m  [NNODES * H];
__device__ float d_agg[NNODES * H];
__device__ float d_v  [NNODES * H];
__device__ float d_vt [NNODES * H];
__device__ float d_sh [BATCH  * H];
// bf16 hi/lo split operands
__device__ __nv_bfloat16 d_ehi[(size_t)JPAD * KP];
__device__ __nv_bfloat16 d_elo[(size_t)JPAD * KP];
__device__ __nv_bfloat16 d_bhi[BATCH * BROWS * BSTRIDE];
__device__ __nv_bfloat16 d_blo[BATCH * BROWS * BSTRIDE];

// ------------------------------------------------------------------
// K1: h = embed[x];  m = h @ ggc_w[0];  agg = 0
// ------------------------------------------------------------------
__global__ void k1_gather_m(const int* __restrict__ x,
                            const float* __restrict__ embed,
                            const float* __restrict__ ggc)
{
    int i = blockIdx.x;
    int t = threadIdx.x;
    __shared__ float hs[H];
    int xi = x[i];
    if (t < H) {
        float val = embed[(size_t)xi * H + t];
        hs[t] = val;
        d_h[i * H + t] = val;
    }
    __syncthreads();
    if (t < H) {
        float acc = 0.f;
        #pragma unroll 4
        for (int k = 0; k < H; k++)
            acc = fmaf(hs[k], ggc[k * H + t], acc);
        d_m[i * H + t]   = acc;
        d_agg[i * H + t] = 0.f;
    }
}

// ------------------------------------------------------------------
// K2: agg[dst] += w_e * m[src]
// ------------------------------------------------------------------
__global__ void k2_scatter(const int* __restrict__ ei,
                           const float* __restrict__ ew)
{
    int idx = blockIdx.x * blockDim.x + threadIdx.x;
    if (idx >= EDGES * H) return;
    int e = idx / H;
    int h = idx - e * H;
    int src = ei[e];
    int dst = ei[EDGES + e];
    atomicAdd(&d_agg[dst * H + h], ew[e] * d_m[src * H + h]);
}

// ------------------------------------------------------------------
// K3: GRU + fused W2-pre/vt (unchanged, known-good)
// ------------------------------------------------------------------
__global__ void __launch_bounds__(128)
k3_gru_post(const float* __restrict__ wih,
            const float* __restrict__ whh,
            const float* __restrict__ bih,
            const float* __restrict__ bhh,
            const float* __restrict__ W2,
            const float* __restrict__ b2,
            const float* __restrict__ Wt,
            const float* __restrict__ bt)
{
    int node0 = blockIdx.x * NPB;
    int c = threadIdx.x;
    __shared__ __align__(16) float ag[NPB * H];
    __shared__ __align__(16) float hh[NPB * H];
    __shared__ __align__(16) float vv[NPB * H];

    for (int idx = c; idx < NPB * H; idx += 128) {
        ag[idx] = d_agg[node0 * H + idx];
        hh[idx] = d_h  [node0 * H + idx];
    }
    __syncthreads();

    if (c < H) {
        float air[NPB], aiz[NPB], ain[NPB], ahr[NPB], ahz[NPB], ahn[NPB];
        float br = bih[c], bz = bih[H + c], bn = bih[2 * H + c];
        float cr = bhh[c], cz = bhh[H + c], cn = bhh[2 * H + c];
        #pragma unroll
        for (int n = 0; n < NPB; n++) {
            air[n] = br; aiz[n] = bz; ain[n] = bn;
            ahr[n] = cr; ahz[n] = cz; ahn[n] = cn;
        }
        const float4* wr4 = (const float4*)(wih + (size_t)c * H);
        const float4* wz4 = (const float4*)(wih + (size_t)(H + c) * H);
        const float4* wn4 = (const float4*)(wih + (size_t)(2 * H + c) * H);
        const float4* ur4 = (const float4*)(whh + (size_t)c * H);
        const float4* uz4 = (const float4*)(whh + (size_t)(H + c) * H);
        const float4* un4 = (const float4*)(whh + (size_t)(2 * H + c) * H);

        for (int k = 0; k < H4; k++) {
            float4 wr = wr4[k], wz = wz4[k], wn = wn4[k];
            float4 ur = ur4[k], uz = uz4[k], un = un4[k];
            #pragma unroll
            for (int n = 0; n < NPB; n++) {
                float4 a  = *(const float4*)&ag[n * H + 4 * k];
                float4 hv = *(const float4*)&hh[n * H + 4 * k];
                air[n] = fmaf(a.x, wr.x, air[n]); air[n] = fmaf(a.y, wr.y, air[n]);
                air[n] = fmaf(a.z, wr.z, air[n]); air[n] = fmaf(a.w, wr.w, air[n]);
                aiz[n] = fmaf(a.x, wz.x, aiz[n]); aiz[n] = fmaf(a.y, wz.y, aiz[n]);
                aiz[n] = fmaf(a.z, wz.z, aiz[n]); aiz[n] = fmaf(a.w, wz.w, aiz[n]);
                ain[n] = fmaf(a.x, wn.x, ain[n]); ain[n] = fmaf(a.y, wn.y, ain[n]);
                ain[n] = fmaf(a.z, wn.z, ain[n]); ain[n] = fmaf(a.w, wn.w, ain[n]);
                ahr[n] = fmaf(hv.x, ur.x, ahr[n]); ahr[n] = fmaf(hv.y, ur.y, ahr[n]);
                ahr[n] = fmaf(hv.z, ur.z, ahr[n]); ahr[n] = fmaf(hv.w, ur.w, ahr[n]);
                ahz[n] = fmaf(hv.x, uz.x, ahz[n]); ahz[n] = fmaf(hv.y, uz.y, ahz[n]);
                ahz[n] = fmaf(hv.z, uz.z, ahz[n]); ahz[n] = fmaf(hv.w, uz.w, ahz[n]);
                ahn[n] = fmaf(hv.x, un.x, ahn[n]); ahn[n] = fmaf(hv.y, un.y, ahn[n]);
                ahn[n] = fmaf(hv.z, un.z, ahn[n]); ahn[n] = fmaf(hv.w, un.w, ahn[n]);
            }
        }
        #pragma unroll
        for (int n = 0; n < NPB; n++) {
            float r  = 1.f / (1.f + __expf(-(air[n] + ahr[n])));
            float zg = 1.f / (1.f + __expf(-(aiz[n] + ahz[n])));
            float ng = tanhf(ain[n] + r * ahn[n]);
            float nv = (1.f - zg) * ng + zg * hh[n * H + c];
            vv[n * H + c] = nv;
            d_v[(node0 + n) * H + c] = nv;
        }
    }
    __syncthreads();

    if (c < H) {
        float a2[NPB], a3[NPB];
        float bb2 = b2[c], bbt = bt[c];
        #pragma unroll
        for (int n = 0; n < NPB; n++) { a2[n] = bb2; a3[n] = bbt; }
        const float4* w2r = (const float4*)(W2 + (size_t)c * H);
        const float4* wtr = (const float4*)(Wt + (size_t)c * H);
        for (int k = 0; k < H4; k++) {
            float4 w2 = w2r[k], wt = wtr[k];
            #pragma unroll
            for (int n = 0; n < NPB; n++) {
                float4 v = *(const float4*)&vv[n * H + 4 * k];
                a2[n] = fmaf(v.x, w2.x, a2[n]); a2[n] = fmaf(v.y, w2.y, a2[n]);
                a2[n] = fmaf(v.z, w2.z, a2[n]); a2[n] = fmaf(v.w, w2.w, a2[n]);
                a3[n] = fmaf(v.x, wt.x, a3[n]); a3[n] = fmaf(v.y, wt.y, a3[n]);
                a3[n] = fmaf(v.z, wt.z, a3[n]); a3[n] = fmaf(v.w, wt.w, a3[n]);
            }
        }
        #pragma unroll
        for (int n = 0; n < NPB; n++) {
            d_m [(node0 + n) * H + c] = a2[n];
            d_vt[(node0 + n) * H + c] = a3[n];
        }
    }
}

// ------------------------------------------------------------------
// K4: per-batch light reductions -> d_sh (unchanged)
// ------------------------------------------------------------------
__global__ void k4_attn(const float* __restrict__ W1, const float* __restrict__ b1,
                        const float* __restrict__ qw, const float* __restrict__ qb,
                        const float* __restrict__ W3, const float* __restrict__ b3)
{
    int b = blockIdx.x;
    int t = threadIdx.x;
    __shared__ __align__(16) float sl[H];
    __shared__ float w1s[H];
    __shared__ float as[LSEQ * H];
    __shared__ float alpha[LSEQ];
    __shared__ __align__(16) float sg[H];

    if (t < H) sl[t] = d_v[(b * LSEQ + LSEQ - 1) * H + t];
    __syncthreads();

    if (t < H) {
        float acc = b1[t];
        const float4* w = (const float4*)(W1 + (size_t)t * H);
        for (int k = 0; k < H4; k++) {
            float4 wv = w[k];
            float4 s = *(const float4*)&sl[4 * k];
            acc = fmaf(s.x, wv.x, acc); acc = fmaf(s.y, wv.y, acc);
            acc = fmaf(s.z, wv.z, acc); acc = fmaf(s.w, wv.w, acc);
        }
        w1s[t] = acc;
    }
    __syncthreads();

    for (int idx = t; idx < LSEQ * H; idx += blockDim.x) {
        int l = idx / H, hh2 = idx - l * H;
        float pre = d_m[(b * LSEQ + l) * H + hh2];
        as[idx] = 1.f / (1.f + __expf(-(w1s[hh2] + pre)));
    }
    __syncthreads();

    if (t < LSEQ) {
        float acc = qb[0];
        for (int k = 0; k < H; k++) acc = fmaf(as[t * H + k], qw[k], acc);
        alpha[t] = acc;
    }
    __syncthreads();

    if (t < H) {
        float acc = 0.f;
        for (int l = 0; l < LSEQ; l++) acc = fmaf(alpha[l], d_v[(b * LSEQ + l) * H + t], acc);
        sg[t] = acc;
    }
    __syncthreads();

    if (t < H) {
        float acc = b3[t];
        const float4* w  = (const float4*)(W3 + (size_t)t * 2 * H);
        for (int k = 0; k < H4; k++) {
            float4 wv = w[k];
            float4 s = *(const float4*)&sl[4 * k];
            acc = fmaf(s.x, wv.x, acc); acc = fmaf(s.y, wv.y, acc);
            acc = fmaf(s.z, wv.z, acc); acc = fmaf(s.w, wv.w, acc);
        }
        for (int k = 0; k < H4; k++) {
            float4 wv = w[H4 + k];
            float4 s = *(const float4*)&sg[4 * k];
            acc = fmaf(s.x, wv.x, acc); acc = fmaf(s.y, wv.y, acc);
            acc = fmaf(s.z, wv.z, acc); acc = fmaf(s.w, wv.w, acc);
        }
        d_sh[b * H + t] = acc;
    }
}

// ------------------------------------------------------------------
// P1: bf16 hi/lo split of embed -> [JPAD, KP], zero-padded
// ------------------------------------------------------------------
__global__ void p1_split_embed(const float* __restrict__ embed)
{
    int idx = blockIdx.x * blockDim.x + threadIdx.x;
    if (idx >= JPAD * KP) return;
    int row = idx / KP, k = idx - row * KP;
    float val = (row < NNODE && k < H) ? embed[(size_t)row * H + k] : 0.f;
    __nv_bfloat16 hi = __float2bfloat16(val);
    d_ehi[idx] = hi;
    d_elo[idx] = __float2bfloat16(val - __bfloat162float(hi));
}

// ------------------------------------------------------------------
// P2: B matrix rows [b][n][k]: n<16 -> vt, n<32 -> v, n==32 -> sh, else 0
// ------------------------------------------------------------------
__global__ void p2_split_b()
{
    int idx = blockIdx.x * blockDim.x + threadIdx.x;
    if (idx >= BATCH * BROWS * BSTRIDE) return;
    int k = idx % BSTRIDE;
    int r = idx / BSTRIDE;
    int n = r % BROWS;
    int b = r / BROWS;
    float val = 0.f;
    if (k < H) {
        if (n < 16)       val = d_vt[(b * LSEQ + n) * H + k];
        else if (n < 32)  val = d_v [(b * LSEQ + (n - 16)) * H + k];
        else if (n == 32) val = d_sh[b * H + k];
    }
    __nv_bfloat16 hi = __float2bfloat16(val);
    d_bhi[idx] = hi;
    d_blo[idx] = __float2bfloat16(val - __bfloat162float(hi));
}

// ------------------------------------------------------------------
// K5: tensor-core fused GEMM + softmax epilogue via mma.sync (HMMA).
// Per CTA: 128 j-rows (8 warps x m16). A-frags (hi/lo) register-resident
// across all 64 batches. Per batch: double-buffered smem B (40x120 bf16,
// hi+lo), 7 ksteps x 5 ntiles x 3 split-products HMMA, then quad-shfl
// softmax epilogue. D cols: [0,16)=P logits, [16,32)=C, 32=base.
// ------------------------------------------------------------------
#define BQ (BROWS * BSTRIDE)   // 4800 bf16 per split per batch

__global__ void __launch_bounds__(256, 2)
k5_hmma(float* __restrict__ out)
{
    __shared__ __align__(16) __nv_bfloat16 sb_hi[2][BQ];
    __shared__ __align__(16) __nv_bfloat16 sb_lo[2][BQ];

    int tid  = threadIdx.x;
    int wid  = tid >> 5;
    int lane = tid & 31;
    int grp  = lane >> 2;      // groupID (row within m16 quad structure)
    int qid  = lane & 3;       // thread-in-group
    int tile = blockIdx.x;

    // ---- load A fragments (hi/lo), resident across all batches ----
    // a[ks][0]: (row=grp,   k=2q)   a[ks][1]: (row=grp+8, k=2q)
    // a[ks][2]: (row=grp,   k=2q+8) a[ks][3]: (row=grp+8, k=2q+8)
    uint32_t ahi[KSTEPS][4], alo[KSTEPS][4];
    {
        int r0 = tile * MT + wid * 16 + grp;
        int r1 = r0 + 8;
        #pragma unroll
        for (int ks = 0; ks < KSTEPS; ks++) {
            int k0 = ks * 16 + 2 * qid;
            ahi[ks][0] = *(const uint32_t*)(d_ehi + (size_t)r0 * KP + k0);
            ahi[ks][1] = *(const uint32_t*)(d_ehi + (size_t)r1 * KP + k0);
            ahi[ks][2] = *(const uint32_t*)(d_ehi + (size_t)r0 * KP + k0 + 8);
            ahi[ks][3] = *(const uint32_t*)(d_ehi + (size_t)r1 * KP + k0 + 8);
            alo[ks][0] = *(const uint32_t*)(d_elo + (size_t)r0 * KP + k0);
            alo[ks][1] = *(const uint32_t*)(d_elo + (size_t)r1 * KP + k0);
            alo[ks][2] = *(const uint32_t*)(d_elo + (size_t)r0 * KP + k0 + 8);
            alo[ks][3] = *(const uint32_t*)(d_elo + (size_t)r1 * KP + k0 + 8);
        }
    }

    // prime buffer 0 with batch 0
    {
        const uint4* sh = (const uint4*)d_bhi;
        const uint4* sl = (const uint4*)d_blo;
        uint4* dh = (uint4*)sb_hi[0];
        uint4* dl = (uint4*)sb_lo[0];
        for (int i = tid; i < BQ / 8; i += 256) { dh[i] = sh[i]; dl[i] = sl[i]; }
    }
    __syncthreads();

    int j0 = tile * MT + wid * 16 + grp;   // global row for grp
    int j1 = j0 + 8;

    #pragma unroll 1
    for (int b = 0; b < BATCH; b++) {
        int cur = b & 1;
        // fill next buffer (overlaps compute on cur)
        if (b + 1 < BATCH) {
            const uint4* sh = (const uint4*)(d_bhi + (size_t)(b + 1) * BQ);
            const uint4* sl = (const uint4*)(d_blo + (size_t)(b + 1) * BQ);
            uint4* dh = (uint4*)sb_hi[cur ^ 1];
            uint4* dl = (uint4*)sb_lo[cur ^ 1];
            for (int i = tid; i < BQ / 8; i += 256) { dh[i] = sh[i]; dl[i] = sl[i]; }
        }

        // ---- MMA mainloop ----
        float D[NTL][4];
        #pragma unroll
        for (int nt = 0; nt < NTL; nt++)
            { D[nt][0] = 0.f; D[nt][1] = 0.f; D[nt][2] = 0.f; D[nt][3] = 0.f; }

        const __nv_bfloat16* Bh = sb_hi[cur];
        const __nv_bfloat16* Bl = sb_lo[cur];

        #pragma unroll
        for (int ks = 0; ks < KSTEPS; ks++) {
            int kb = ks * 16 + 2 * qid;
            #pragma unroll
            for (int nt = 0; nt < NTL; nt++) {
                int n = nt * 8 + grp;
                uint32_t bh0 = *(const uint32_t*)(Bh + n * BSTRIDE + kb);
                uint32_t bh1 = *(const uint32_t*)(Bh + n * BSTRIDE + kb + 8);
                uint32_t bl0 = *(const uint32_t*)(Bl + n * BSTRIDE + kb);
                uint32_t bl1 = *(const uint32_t*)(Bl + n * BSTRIDE + kb + 8);
                MMA16816(D[nt], ahi[ks], bh0, bh1);   // hi*hi
                MMA16816(D[nt], ahi[ks], bl0, bl1);   // hi*lo
                MMA16816(D[nt], alo[ks], bh0, bh1);   // lo*hi
            }
        }

        // ---- epilogue: per-row softmax over 16 P cols, weight C, add base ----
        // row0 = grp: regs [..][0],[..][1]; row1 = grp+8: regs [..][2],[..][3]
        // thread's l cols: tile0 -> {2q, 2q+1}, tile1 -> {8+2q, 8+2q+1}
        {
            // row 0
            float m0 = fmaxf(fmaxf(D[0][0], D[0][1]), fmaxf(D[1][0], D[1][1]));
            m0 = fmaxf(m0, __shfl_xor_sync(0xffffffffu, m0, 1));
            m0 = fmaxf(m0, __shfl_xor_sync(0xffffffffu, m0, 2));
            float e00 = __expf(D[0][0] - m0), e01 = __expf(D[0][1] - m0);
            float e10 = __expf(D[1][0] - m0), e11 = __expf(D[1][1] - m0);
            float es0 = (e00 + e01) + (e10 + e11);
            float ws0 = fmaf(e00, D[2][0], fmaf(e01, D[2][1],
                        fmaf(e10, D[3][0], e11 * D[3][1])));
            es0 += __shfl_xor_sync(0xffffffffu, es0, 1);
            es0 += __shfl_xor_sync(0xffffffffu, es0, 2);
            ws0 += __shfl_xor_sync(0xffffffffu, ws0, 1);
            ws0 += __shfl_xor_sync(0xffffffffu, ws0, 2);
            float base0 = __shfl_sync(0xffffffffu, D[4][0], lane & ~3);

            // row 1
            float m1 = fmaxf(fmaxf(D[0][2], D[0][3]), fmaxf(D[1][2], D[1][3]));
            m1 = fmaxf(m1, __shfl_xor_sync(0xffffffffu, m1, 1));
            m1 = fmaxf(m1, __shfl_xor_sync(0xffffffffu, m1, 2));
            float f00 = __expf(D[0][2] - m1), f01 = __expf(D[0][3] - m1);
            float f10 = __expf(D[1][2] - m1), f11 = __expf(D[1][3] - m1);
            float es1 = (f00 + f01) + (f10 + f11);
            float ws1 = fmaf(f00, D[2][2], fmaf(f01, D[2][3],
                        fmaf(f10, D[3][2], f11 * D[3][3])));
            es1 += __shfl_xor_sync(0xffffffffu, es1, 1);
            es1 += __shfl_xor_sync(0xffffffffu, es1, 2);
            ws1 += __shfl_xor_sync(0xffffffffu, ws1, 1);
            ws1 += __shfl_xor_sync(0xffffffffu, ws1, 2);
            float base1 = __shfl_sync(0xffffffffu, D[4][2], lane & ~3);

            if (qid == 0) {
                if (j0 < NNODE) out[(size_t)b * NNODE + j0] = base0 + ws0 / es0;
                if (j1 < NNODE) out[(size_t)b * NNODE + j1] = base1 + ws1 / es1;
            }
        }
        __syncthreads();   // everyone done with cur before it's refilled
    }
}

// ------------------------------------------------------------------
extern "C" void kernel_launch(void* const* d_in, const int* in_sizes, int n_in,
                              void* d_out, int out_size)
{
    const int*   x     = (const int*)  d_in[0];
    const int*   ei    = (const int*)  d_in[1];
    const float* ew    = (const float*)d_in[2];
    // d_in[3] = batch (unused)
    const float* embed = (const float*)d_in[4];
    const float* ggc   = (const float*)d_in[5];
    const float* wih   = (const float*)d_in[6];
    const float* whh   = (const float*)d_in[7];
    const float* bih   = (const float*)d_in[8];
    const float* bhh   = (const float*)d_in[9];
    const float* W1    = (const float*)d_in[10];
    const float* b1    = (const float*)d_in[11];
    const float* W2    = (const float*)d_in[12];
    const float* b2    = (const float*)d_in[13];
    const float* Wt    = (const float*)d_in[14];
    const float* bt    = (const float*)d_in[15];
    const float* qw    = (const float*)d_in[16];
    const float* qb    = (const float*)d_in[17];
    const float* W3    = (const float*)d_in[18];
    const float* b3    = (const float*)d_in[19];
    float* out = (float*)d_out;

    k1_gather_m<<<NNODES, 128>>>(x, embed, ggc);
    k2_scatter <<<(EDGES * H + 255) / 256, 256>>>(ei, ew);
    p1_split_embed<<<(JPAD * KP + 255) / 256, 256>>>(embed);
    k3_gru_post<<<NNODES / NPB, 128>>>(wih, whh, bih, bhh, W2, b2, Wt, bt);
    k4_attn    <<<BATCH, 128>>>(W1, b1, qw, qb, W3, b3);
    p2_split_b <<<(BATCH * BROWS * BSTRIDE + 255) / 256, 256>>>();
    k5_hmma    <<<NTILES, 256>>>(out);
}

// round 7
// speedup vs baseline: 4.5438x; 1.1419x over previous
#include <cuda_runtime.h>
#include <cuda_bf16.h>
#include <math.h>
#include <cstdint>

#define H       100
#define NNODES  1024    // N = B*L
#define BATCH   64
#define LSEQ    16
#define EDGES   2048
#define NNODE   40000
#define H4      25
#define NPB     4       // nodes per block in k3

// ---- mma.sync GEMM config ----
#define MT      128                // j rows per CTA (8 warps x m16)
#define NTILES  313                // ceil(40000/128)
#define JPAD    (NTILES * MT)      // 40064
#define KP      112                // padded K (7 k-steps of 16)
#define KSTEPS  7
#define BROWS   32                 // B rows per batch: 16 vt | 16 v
#define BSTRIDE 120                // B row stride in bf16 (bank-conflict-free)
#define NTL     4                  // n8 tiles per batch: 16 P + 16 C

typedef unsigned long long ull;

#define MMA16816(d, a, b0, b1)                                              \
    asm volatile("mma.sync.aligned.m16n8k16.row.col.f32.bf16.bf16.f32 "     \
        "{%0,%1,%2,%3}, {%4,%5,%6,%7}, {%8,%9}, {%0,%1,%2,%3};"             \
        : "+f"((d)[0]), "+f"((d)[1]), "+f"((d)[2]), "+f"((d)[3])            \
        : "r"((a)[0]), "r"((a)[1]), "r"((a)[2]), "r"((a)[3]),               \
          "r"(b0), "r"(b1))

// ---- scratch (no allocations allowed) ----
__device__ float d_h  [NNODES * H];
__device__ float d_m  [NNODES * H];
__device__ float d_agg[NNODES * H];
__device__ float d_v  [NNODES * H];
__device__ float d_vt [NNODES * H];
__device__ float d_sh [BATCH  * H];
// bf16 hi/lo split operands
__device__ __nv_bfloat16 d_ehi[(size_t)JPAD * KP];
__device__ __nv_bfloat16 d_elo[(size_t)JPAD * KP];
__device__ __nv_bfloat16 d_bhi[BATCH * BROWS * BSTRIDE];
__device__ __nv_bfloat16 d_blo[BATCH * BROWS * BSTRIDE];
__device__ __nv_bfloat16 d_shhi[BATCH * BSTRIDE];
__device__ __nv_bfloat16 d_shlo[BATCH * BSTRIDE];

// ------------------------------------------------------------------
// K1: h = embed[x];  m = h @ ggc_w[0];  agg = 0
// ------------------------------------------------------------------
__global__ void k1_gather_m(const int* __restrict__ x,
                            const float* __restrict__ embed,
                            const float* __restrict__ ggc)
{
    int i = blockIdx.x;
    int t = threadIdx.x;
    __shared__ float hs[H];
    int xi = x[i];
    if (t < H) {
        float val = embed[(size_t)xi * H + t];
        hs[t] = val;
        d_h[i * H + t] = val;
    }
    __syncthreads();
    if (t < H) {
        float acc = 0.f;
        #pragma unroll 4
        for (int k = 0; k < H; k++)
            acc = fmaf(hs[k], ggc[k * H + t], acc);
        d_m[i * H + t]   = acc;
        d_agg[i * H + t] = 0.f;
    }
}

// ------------------------------------------------------------------
// K2: agg[dst] += w_e * m[src]
// ------------------------------------------------------------------
__global__ void k2_scatter(const int* __restrict__ ei,
                           const float* __restrict__ ew)
{
    int idx = blockIdx.x * blockDim.x + threadIdx.x;
    if (idx >= EDGES * H) return;
    int e = idx / H;
    int h = idx - e * H;
    int src = ei[e];
    int dst = ei[EDGES + e];
    atomicAdd(&d_agg[dst * H + h], ew[e] * d_m[src * H + h]);
}

// ------------------------------------------------------------------
// K3: GRU + fused W2-pre/vt. NPB=4 -> 256 CTAs (2x occupancy vs R6).
// ------------------------------------------------------------------
__global__ void __launch_bounds__(128)
k3_gru_post(const float* __restrict__ wih,
            const float* __restrict__ whh,
            const float* __restrict__ bih,
            const float* __restrict__ bhh,
            const float* __restrict__ W2,
            const float* __restrict__ b2,
            const float* __restrict__ Wt,
            const float* __restrict__ bt)
{
    int node0 = blockIdx.x * NPB;
    int c = threadIdx.x;
    __shared__ __align__(16) float ag[NPB * H];
    __shared__ __align__(16) float hh[NPB * H];
    __shared__ __align__(16) float vv[NPB * H];

    for (int idx = c; idx < NPB * H; idx += 128) {
        ag[idx] = d_agg[node0 * H + idx];
        hh[idx] = d_h  [node0 * H + idx];
    }
    __syncthreads();

    if (c < H) {
        float air[NPB], aiz[NPB], ain[NPB], ahr[NPB], ahz[NPB], ahn[NPB];
        float br = bih[c], bz = bih[H + c], bn = bih[2 * H + c];
        float cr = bhh[c], cz = bhh[H + c], cn = bhh[2 * H + c];
        #pragma unroll
        for (int n = 0; n < NPB; n++) {
            air[n] = br; aiz[n] = bz; ain[n] = bn;
            ahr[n] = cr; ahz[n] = cz; ahn[n] = cn;
        }
        const float4* wr4 = (const float4*)(wih + (size_t)c * H);
        const float4* wz4 = (const float4*)(wih + (size_t)(H + c) * H);
        const float4* wn4 = (const float4*)(wih + (size_t)(2 * H + c) * H);
        const float4* ur4 = (const float4*)(whh + (size_t)c * H);
        const float4* uz4 = (const float4*)(whh + (size_t)(H + c) * H);
        const float4* un4 = (const float4*)(whh + (size_t)(2 * H + c) * H);

        for (int k = 0; k < H4; k++) {
            float4 wr = wr4[k], wz = wz4[k], wn = wn4[k];
            float4 ur = ur4[k], uz = uz4[k], un = un4[k];
            #pragma unroll
            for (int n = 0; n < NPB; n++) {
                float4 a  = *(const float4*)&ag[n * H + 4 * k];
                float4 hv = *(const float4*)&hh[n * H + 4 * k];
                air[n] = fmaf(a.x, wr.x, air[n]); air[n] = fmaf(a.y, wr.y, air[n]);
                air[n] = fmaf(a.z, wr.z, air[n]); air[n] = fmaf(a.w, wr.w, air[n]);
                aiz[n] = fmaf(a.x, wz.x, aiz[n]); aiz[n] = fmaf(a.y, wz.y, aiz[n]);
                aiz[n] = fmaf(a.z, wz.z, aiz[n]); aiz[n] = fmaf(a.w, wz.w, aiz[n]);
                ain[n] = fmaf(a.x, wn.x, ain[n]); ain[n] = fmaf(a.y, wn.y, ain[n]);
                ain[n] = fmaf(a.z, wn.z, ain[n]); ain[n] = fmaf(a.w, wn.w, ain[n]);
                ahr[n] = fmaf(hv.x, ur.x, ahr[n]); ahr[n] = fmaf(hv.y, ur.y, ahr[n]);
                ahr[n] = fmaf(hv.z, ur.z, ahr[n]); ahr[n] = fmaf(hv.w, ur.w, ahr[n]);
                ahz[n] = fmaf(hv.x, uz.x, ahz[n]); ahz[n] = fmaf(hv.y, uz.y, ahz[n]);
                ahz[n] = fmaf(hv.z, uz.z, ahz[n]); ahz[n] = fmaf(hv.w, uz.w, ahz[n]);
                ahn[n] = fmaf(hv.x, un.x, ahn[n]); ahn[n] = fmaf(hv.y, un.y, ahn[n]);
                ahn[n] = fmaf(hv.z, un.z, ahn[n]); ahn[n] = fmaf(hv.w, un.w, ahn[n]);
            }
        }
        #pragma unroll
        for (int n = 0; n < NPB; n++) {
            float r  = 1.f / (1.f + __expf(-(air[n] + ahr[n])));
            float zg = 1.f / (1.f + __expf(-(aiz[n] + ahz[n])));
            float ng = tanhf(ain[n] + r * ahn[n]);
            float nv = (1.f - zg) * ng + zg * hh[n * H + c];
            vv[n * H + c] = nv;
            d_v[(node0 + n) * H + c] = nv;
        }
    }
    __syncthreads();

    if (c < H) {
        float a2[NPB], a3[NPB];
        float bb2 = b2[c], bbt = bt[c];
        #pragma unroll
        for (int n = 0; n < NPB; n++) { a2[n] = bb2; a3[n] = bbt; }
        const float4* w2r = (const float4*)(W2 + (size_t)c * H);
        const float4* wtr = (const float4*)(Wt + (size_t)c * H);
        for (int k = 0; k < H4; k++) {
            float4 w2 = w2r[k], wt = wtr[k];
            #pragma unroll
            for (int n = 0; n < NPB; n++) {
                float4 v = *(const float4*)&vv[n * H + 4 * k];
                a2[n] = fmaf(v.x, w2.x, a2[n]); a2[n] = fmaf(v.y, w2.y, a2[n]);
                a2[n] = fmaf(v.z, w2.z, a2[n]); a2[n] = fmaf(v.w, w2.w, a2[n]);
                a3[n] = fmaf(v.x, wt.x, a3[n]); a3[n] = fmaf(v.y, wt.y, a3[n]);
                a3[n] = fmaf(v.z, wt.z, a3[n]); a3[n] = fmaf(v.w, wt.w, a3[n]);
            }
        }
        #pragma unroll
        for (int n = 0; n < NPB; n++) {
            d_m [(node0 + n) * H + c] = a2[n];
            d_vt[(node0 + n) * H + c] = a3[n];
        }
    }
}

// ------------------------------------------------------------------
// K4: per-batch light reductions -> d_sh (unchanged)
// ------------------------------------------------------------------
__global__ void k4_attn(const float* __restrict__ W1, const float* __restrict__ b1,
                        const float* __restrict__ qw, const float* __restrict__ qb,
                        const float* __restrict__ W3, const float* __restrict__ b3)
{
    int b = blockIdx.x;
    int t = threadIdx.x;
    __shared__ __align__(16) float sl[H];
    __shared__ float w1s[H];
    __shared__ float as[LSEQ * H];
    __shared__ float alpha[LSEQ];
    __shared__ __align__(16) float sg[H];

    if (t < H) sl[t] = d_v[(b * LSEQ + LSEQ - 1) * H + t];
    __syncthreads();

    if (t < H) {
        float acc = b1[t];
        const float4* w = (const float4*)(W1 + (size_t)t * H);
        for (int k = 0; k < H4; k++) {
            float4 wv = w[k];
            float4 s = *(const float4*)&sl[4 * k];
            acc = fmaf(s.x, wv.x, acc); acc = fmaf(s.y, wv.y, acc);
            acc = fmaf(s.z, wv.z, acc); acc = fmaf(s.w, wv.w, acc);
        }
        w1s[t] = acc;
    }
    __syncthreads();

    for (int idx = t; idx < LSEQ * H; idx += blockDim.x) {
        int l = idx / H, hh2 = idx - l * H;
        float pre = d_m[(b * LSEQ + l) * H + hh2];
        as[idx] = 1.f / (1.f + __expf(-(w1s[hh2] + pre)));
    }
    __syncthreads();

    if (t < LSEQ) {
        float acc = qb[0];
        for (int k = 0; k < H; k++) acc = fmaf(as[t * H + k], qw[k], acc);
        alpha[t] = acc;
    }
    __syncthreads();

    if (t < H) {
        float acc = 0.f;
        for (int l = 0; l < LSEQ; l++) acc = fmaf(alpha[l], d_v[(b * LSEQ + l) * H + t], acc);
        sg[t] = acc;
    }
    __syncthreads();

    if (t < H) {
        float acc = b3[t];
        const float4* w  = (const float4*)(W3 + (size_t)t * 2 * H);
        for (int k = 0; k < H4; k++) {
            float4 wv = w[k];
            float4 s = *(const float4*)&sl[4 * k];
            acc = fmaf(s.x, wv.x, acc); acc = fmaf(s.y, wv.y, acc);
            acc = fmaf(s.z, wv.z, acc); acc = fmaf(s.w, wv.w, acc);
        }
        for (int k = 0; k < H4; k++) {
            float4 wv = w[H4 + k];
            float4 s = *(const float4*)&sg[4 * k];
            acc = fmaf(s.x, wv.x, acc); acc = fmaf(s.y, wv.y, acc);
            acc = fmaf(s.z, wv.z, acc); acc = fmaf(s.w, wv.w, acc);
        }
        d_sh[b * H + t] = acc;
    }
}

// ------------------------------------------------------------------
// P1: bf16 hi/lo split of embed -> [JPAD, KP], zero-padded
// ------------------------------------------------------------------
__global__ void p1_split_embed(const float* __restrict__ embed)
{
    int idx = blockIdx.x * blockDim.x + threadIdx.x;
    if (idx >= JPAD * KP) return;
    int row = idx / KP, k = idx - row * KP;
    float val = (row < NNODE && k < H) ? embed[(size_t)row * H + k] : 0.f;
    __nv_bfloat16 hi = __float2bfloat16(val);
    d_ehi[idx] = hi;
    d_elo[idx] = __float2bfloat16(val - __bfloat162float(hi));
}

// ------------------------------------------------------------------
// P2: B rows [b][n][k]: n<16 -> vt, else v;  plus sh tile [b][k]
// ------------------------------------------------------------------
__global__ void p2_split_b()
{
    int idx = blockIdx.x * blockDim.x + threadIdx.x;
    int nb = BATCH * BROWS * BSTRIDE;
    if (idx < nb) {
        int k = idx % BSTRIDE;
        int r = idx / BSTRIDE;
        int n = r % BROWS;
        int b = r / BROWS;
        float val = 0.f;
        if (k < H)
            val = (n < 16) ? d_vt[(b * LSEQ + n) * H + k]
                           : d_v [(b * LSEQ + (n - 16)) * H + k];
        __nv_bfloat16 hi = __float2bfloat16(val);
        d_bhi[idx] = hi;
        d_blo[idx] = __float2bfloat16(val - __bfloat162float(hi));
    } else {
        int i2 = idx - nb;
        if (i2 < BATCH * BSTRIDE) {
            int k = i2 % BSTRIDE;
            int b = i2 / BSTRIDE;
            float val = (k < H) ? d_sh[b * H + k] : 0.f;
            __nv_bfloat16 hi = __float2bfloat16(val);
            d_shhi[i2] = hi;
            d_shlo[i2] = __float2bfloat16(val - __bfloat162float(hi));
        }
    }
}

// ------------------------------------------------------------------
// K5: tensor-core fused GEMM + softmax epilogue via mma.sync (HMMA).
// Phase 0: base GEMM E_tile . SH^T (all 64 batches) -> smem (128x64,
// stride-65 pad). Main loop: per batch 4 n-tiles (16 vt + 16 v),
// double-buffered smem B, 3-product bf16 split, quad-shfl softmax.
// ------------------------------------------------------------------
#define BQ   (BROWS * BSTRIDE)     // 3840 bf16 per split per batch
#define SHQ  (BATCH * BSTRIDE)     // 7680 bf16 per split (sh tile)
#define BASE_STRIDE 65
// dynamic smem: [0, 30720) B/sh tiles; [30720, 64000) base floats
#define SMEM_K5 (30720 + 128 * BASE_STRIDE * 4)

__global__ void __launch_bounds__(256, 2)
k5_hmma(float* __restrict__ out)
{
    extern __shared__ __align__(16) char dsm[];
    __nv_bfloat16* sb = (__nv_bfloat16*)dsm;          // 15360 bf16
    float* s_base = (float*)(dsm + 30720);            // 128*65 floats

    int tid  = threadIdx.x;
    int wid  = tid >> 5;
    int lane = tid & 31;
    int grp  = lane >> 2;
    int qid  = lane & 3;
    int tile = blockIdx.x;

    // ---- A fragments (hi/lo), register-resident throughout ----
    uint32_t ahi[KSTEPS][4], alo[KSTEPS][4];
    {
        int r0 = tile * MT + wid * 16 + grp;
        int r1 = r0 + 8;
        #pragma unroll
        for (int ks = 0; ks < KSTEPS; ks++) {
            int k0 = ks * 16 + 2 * qid;
            ahi[ks][0] = *(const uint32_t*)(d_ehi + (size_t)r0 * KP + k0);
            ahi[ks][1] = *(const uint32_t*)(d_ehi + (size_t)r1 * KP + k0);
            ahi[ks][2] = *(const uint32_t*)(d_ehi + (size_t)r0 * KP + k0 + 8);
            ahi[ks][3] = *(const uint32_t*)(d_ehi + (size_t)r1 * KP + k0 + 8);
            alo[ks][0] = *(const uint32_t*)(d_elo + (size_t)r0 * KP + k0);
            alo[ks][1] = *(const uint32_t*)(d_elo + (size_t)r1 * KP + k0);
            alo[ks][2] = *(const uint32_t*)(d_elo + (size_t)r0 * KP + k0 + 8);
            alo[ks][3] = *(const uint32_t*)(d_elo + (size_t)r1 * KP + k0 + 8);
        }
    }

    // ================= PHASE 0: base GEMM (E . SH^T) =================
    {
        const uint4* shh = (const uint4*)d_shhi;
        const uint4* shl = (const uint4*)d_shlo;
        uint4* dh = (uint4*)sb;                 // hi: 64x120 at offset 0
        uint4* dl = (uint4*)(sb + SHQ);         // lo: 64x120 at +7680
        for (int i = tid; i < SHQ / 8; i += 256) { dh[i] = shh[i]; dl[i] = shl[i]; }
        __syncthreads();

        float Db[8][4];
        #pragma unroll
        for (int nt = 0; nt < 8; nt++)
            { Db[nt][0] = 0.f; Db[nt][1] = 0.f; Db[nt][2] = 0.f; Db[nt][3] = 0.f; }

        #pragma unroll
        for (int ks = 0; ks < KSTEPS; ks++) {
            int kb = ks * 16 + 2 * qid;
            #pragma unroll
            for (int nt = 0; nt < 8; nt++) {
                int n = nt * 8 + grp;
                uint32_t bh0 = *(const uint32_t*)(sb + n * BSTRIDE + kb);
                uint32_t bh1 = *(const uint32_t*)(sb + n * BSTRIDE + kb + 8);
                uint32_t bl0 = *(const uint32_t*)(sb + SHQ + n * BSTRIDE + kb);
                uint32_t bl1 = *(const uint32_t*)(sb + SHQ + n * BSTRIDE + kb + 8);
                MMA16816(Db[nt], ahi[ks], bh0, bh1);
                MMA16816(Db[nt], ahi[ks], bl0, bl1);
                MMA16816(Db[nt], alo[ks], bh0, bh1);
            }
        }
        int r0 = wid * 16 + grp, r1 = r0 + 8;
        #pragma unroll
        for (int nt = 0; nt < 8; nt++) {
            int c0 = nt * 8 + 2 * qid;
            s_base[r0 * BASE_STRIDE + c0]     = Db[nt][0];
            s_base[r0 * BASE_STRIDE + c0 + 1] = Db[nt][1];
            s_base[r1 * BASE_STRIDE + c0]     = Db[nt][2];
            s_base[r1 * BASE_STRIDE + c0 + 1] = Db[nt][3];
        }
        __syncthreads();
    }

    // prime buffer 0 with batch 0
    {
        const uint4* sh = (const uint4*)d_bhi;
        const uint4* sl = (const uint4*)d_blo;
        uint4* dh = (uint4*)sb;
        uint4* dl = (uint4*)(sb + BQ);
        for (int i = tid; i < BQ / 8; i += 256) { dh[i] = sh[i]; dl[i] = sl[i]; }
    }
    __syncthreads();

    int rl0 = wid * 16 + grp;              // local row
    int j0 = tile * MT + rl0;              // global row
    int j1 = j0 + 8;

    #pragma unroll 1
    for (int b = 0; b < BATCH; b++) {
        int cur = b & 1;
        __nv_bfloat16* Bh = sb + cur * (2 * BQ);
        __nv_bfloat16* Bl = Bh + BQ;
        // fill next buffer (overlaps compute on cur)
        if (b + 1 < BATCH) {
            const uint4* sh = (const uint4*)(d_bhi + (size_t)(b + 1) * BQ);
            const uint4* sl = (const uint4*)(d_blo + (size_t)(b + 1) * BQ);
            uint4* dh = (uint4*)(sb + (cur ^ 1) * (2 * BQ));
            uint4* dl = dh + BQ / 8;
            for (int i = tid; i < BQ / 8; i += 256) { dh[i] = sh[i]; dl[i] = sl[i]; }
        }

        // ---- MMA mainloop: 4 n-tiles, products grouped for ILP ----
        float D[NTL][4];
        #pragma unroll
        for (int nt = 0; nt < NTL; nt++)
            { D[nt][0] = 0.f; D[nt][1] = 0.f; D[nt][2] = 0.f; D[nt][3] = 0.f; }

        #pragma unroll
        for (int ks = 0; ks < KSTEPS; ks++) {
            int kb = ks * 16 + 2 * qid;
            uint32_t bh0[NTL], bh1[NTL], bl0[NTL], bl1[NTL];
            #pragma unroll
            for (int nt = 0; nt < NTL; nt++) {
                int n = nt * 8 + grp;
                bh0[nt] = *(const uint32_t*)(Bh + n * BSTRIDE + kb);
                bh1[nt] = *(const uint32_t*)(Bh + n * BSTRIDE + kb + 8);
                bl0[nt] = *(const uint32_t*)(Bl + n * BSTRIDE + kb);
                bl1[nt] = *(const uint32_t*)(Bl + n * BSTRIDE + kb + 8);
            }
            #pragma unroll
            for (int nt = 0; nt < NTL; nt++) MMA16816(D[nt], ahi[ks], bh0[nt], bh1[nt]);
            #pragma unroll
            for (int nt = 0; nt < NTL; nt++) MMA16816(D[nt], ahi[ks], bl0[nt], bl1[nt]);
            #pragma unroll
            for (int nt = 0; nt < NTL; nt++) MMA16816(D[nt], alo[ks], bh0[nt], bh1[nt]);
        }

        // ---- epilogue ----
        {
            float base0 = s_base[rl0 * BASE_STRIDE + b];
            float base1 = s_base[(rl0 + 8) * BASE_STRIDE + b];

            // row 0
            float m0 = fmaxf(fmaxf(D[0][0], D[0][1]), fmaxf(D[1][0], D[1][1]));
            m0 = fmaxf(m0, __shfl_xor_sync(0xffffffffu, m0, 1));
            m0 = fmaxf(m0, __shfl_xor_sync(0xffffffffu, m0, 2));
            float e00 = __expf(D[0][0] - m0), e01 = __expf(D[0][1] - m0);
            float e10 = __expf(D[1][0] - m0), e11 = __expf(D[1][1] - m0);
            float es0 = (e00 + e01) + (e10 + e11);
            float ws0 = fmaf(e00, D[2][0], fmaf(e01, D[2][1],
                        fmaf(e10, D[3][0], e11 * D[3][1])));
            es0 += __shfl_xor_sync(0xffffffffu, es0, 1);
            es0 += __shfl_xor_sync(0xffffffffu, es0, 2);
            ws0 += __shfl_xor_sync(0xffffffffu, ws0, 1);
            ws0 += __shfl_xor_sync(0xffffffffu, ws0, 2);

            // row 1
            float m1 = fmaxf(fmaxf(D[0][2], D[0][3]), fmaxf(D[1][2], D[1][3]));
            m1 = fmaxf(m1, __shfl_xor_sync(0xffffffffu, m1, 1));
            m1 = fmaxf(m1, __shfl_xor_sync(0xffffffffu, m1, 2));
            float f00 = __expf(D[0][2] - m1), f01 = __expf(D[0][3] - m1);
            float f10 = __expf(D[1][2] - m1), f11 = __expf(D[1][3] - m1);
            float es1 = (f00 + f01) + (f10 + f11);
            float ws1 = fmaf(f00, D[2][2], fmaf(f01, D[2][3],
                        fmaf(f10, D[3][2], f11 * D[3][3])));
            es1 += __shfl_xor_sync(0xffffffffu, es1, 1);
            es1 += __shfl_xor_sync(0xffffffffu, es1, 2);
            ws1 += __shfl_xor_sync(0xffffffffu, ws1, 1);
            ws1 += __shfl_xor_sync(0xffffffffu, ws1, 2);

            if (qid == 0) {
                if (j0 < NNODE) out[(size_t)b * NNODE + j0] = base0 + ws0 / es0;
                if (j1 < NNODE) out[(size_t)b * NNODE + j1] = base1 + ws1 / es1;
            }
        }
        __syncthreads();   // everyone done with cur before it's refilled
    }
}

// ------------------------------------------------------------------
extern "C" void kernel_launch(void* const* d_in, const int* in_sizes, int n_in,
                              void* d_out, int out_size)
{
    const int*   x     = (const int*)  d_in[0];
    const int*   ei    = (const int*)  d_in[1];
    const float* ew    = (const float*)d_in[2];
    // d_in[3] = batch (unused)
    const float* embed = (const float*)d_in[4];
    const float* ggc   = (const float*)d_in[5];
    const float* wih   = (const float*)d_in[6];
    const float* whh   = (const float*)d_in[7];
    const float* bih   = (const float*)d_in[8];
    const float* bhh   = (const float*)d_in[9];
    const float* W1    = (const float*)d_in[10];
    const float* b1    = (const float*)d_in[11];
    const float* W2    = (const float*)d_in[12];
    const float* b2    = (const float*)d_in[13];
    const float* Wt    = (const float*)d_in[14];
    const float* bt    = (const float*)d_in[15];
    const float* qw    = (const float*)d_in[16];
    const float* qb    = (const float*)d_in[17];
    const float* W3    = (const float*)d_in[18];
    const float* b3    = (const float*)d_in[19];
    float* out = (float*)d_out;

    cudaFuncSetAttribute(k5_hmma, cudaFuncAttributeMaxDynamicSharedMemorySize, SMEM_K5);

    k1_gather_m<<<NNODES, 128>>>(x, embed, ggc);
    k2_scatter <<<(EDGES * H + 255) / 256, 256>>>(ei, ew);
    p1_split_embed<<<(JPAD * KP + 255) / 256, 256>>>(embed);
    k3_gru_post<<<NNODES / NPB, 128>>>(wih, whh, bih, bhh, W2, b2, Wt, bt);
    k4_attn    <<<BATCH, 128>>>(W1, b1, qw, qb, W3, b3);
    p2_split_b <<<(BATCH * BROWS * BSTRIDE + BATCH * BSTRIDE + 255) / 256, 256>>>();
    k5_hmma    <<<NTILES, 256, SMEM_K5>>>(out);
}

// round 9
// speedup vs baseline: 4.8257x; 1.0620x over previous
#include <cuda_runtime.h>
#include <cuda_bf16.h>
#include <math.h>
#include <cstdint>

#define H       100
#define NNODES  1024    // N = B*L
#define BATCH   64
#define LSEQ    16
#define EDGES   2048
#define NNODE   40000
#define H4      25
#define NPB     2       // nodes per block in k3

// ---- mma.sync GEMM config ----
#define MT      128                // j rows per CTA (8 warps x m16)
#define NTILES  313                // ceil(40000/128)
#define JPAD    (NTILES * MT)      // 40064
#define KP      112                // padded K (7 k-steps of 16)
#define KSTEPS  7
#define BROWS   32                 // B rows per batch: 16 vt | 16 v
#define BSTRIDE 120                // row stride in bf16 (LDSM conflict-free)
#define NTL     4                  // n8 tiles per batch: 16 P + 16 C

typedef unsigned long long ull;

#define MMA16816(d, a, b0, b1)                                              \
    asm volatile("mma.sync.aligned.m16n8k16.row.col.f32.bf16.bf16.f32 "     \
        "{%0,%1,%2,%3}, {%4,%5,%6,%7}, {%8,%9}, {%0,%1,%2,%3};"             \
        : "+f"((d)[0]), "+f"((d)[1]), "+f"((d)[2]), "+f"((d)[3])            \
        : "r"((a)[0]), "r"((a)[1]), "r"((a)[2]), "r"((a)[3]),               \
          "r"(b0), "r"(b1))

#define LDSM4(r0, r1, r2, r3, addr)                                         \
    asm volatile("ldmatrix.sync.aligned.m8n8.x4.shared.b16 {%0,%1,%2,%3}, [%4];" \
        : "=r"(r0), "=r"(r1), "=r"(r2), "=r"(r3) : "r"(addr))

#define CP_ASYNC16(smaddr, gptr)                                            \
    asm volatile("cp.async.cg.shared.global [%0], [%1], 16;"                \
        :: "r"(smaddr), "l"(gptr) : "memory")
#define CP_COMMIT()  asm volatile("cp.async.commit_group;" ::: "memory")
#define CP_WAIT1()   asm volatile("cp.async.wait_group 1;" ::: "memory")
#define CP_WAIT0()   asm volatile("cp.async.wait_group 0;" ::: "memory")

static __device__ __forceinline__ uint32_t smem_u32(const void* p) {
    uint32_t a;
    asm("{ .reg .u64 t; cvta.to.shared.u64 t, %1; cvt.u32.u64 %0, t; }" : "=r"(a) : "l"(p));
    return a;
}

// ---- scratch (no allocations allowed) ----
__device__ float d_h  [NNODES * H];
__device__ float d_m  [NNODES * H];
__device__ float d_agg[NNODES * H];
__device__ float d_v  [NNODES * H];
__device__ float d_vt [NNODES * H];
__device__ float d_sh [BATCH  * H];
// bf16 hi/lo split operands
__device__ __nv_bfloat16 d_ehi[(size_t)JPAD * KP];
__device__ __nv_bfloat16 d_elo[(size_t)JPAD * KP];
__device__ __nv_bfloat16 d_bhi[BATCH * BROWS * BSTRIDE];
__device__ __nv_bfloat16 d_blo[BATCH * BROWS * BSTRIDE];
__device__ __nv_bfloat16 d_shhi[BATCH * BSTRIDE];
__device__ __nv_bfloat16 d_shlo[BATCH * BSTRIDE];

// ------------------------------------------------------------------
// K1: h = embed[x];  m = h @ ggc_w[0];  agg = 0
// ------------------------------------------------------------------
__global__ void k1_gather_m(const int* __restrict__ x,
                            const float* __restrict__ embed,
                            const float* __restrict__ ggc)
{
    int i = blockIdx.x;
    int t = threadIdx.x;
    __shared__ float hs[H];
    int xi = x[i];
    if (t < H) {
        float val = embed[(size_t)xi * H + t];
        hs[t] = val;
        d_h[i * H + t] = val;
    }
    __syncthreads();
    if (t < H) {
        float acc = 0.f;
        #pragma unroll 4
        for (int k = 0; k < H; k++)
            acc = fmaf(hs[k], ggc[k * H + t], acc);
        d_m[i * H + t]   = acc;
        d_agg[i * H + t] = 0.f;
    }
}

// ------------------------------------------------------------------
// K2: agg[dst] += w_e * m[src]
// ------------------------------------------------------------------
__global__ void k2_scatter(const int* __restrict__ ei,
                           const float* __restrict__ ew)
{
    int idx = blockIdx.x * blockDim.x + threadIdx.x;
    if (idx >= EDGES * H) return;
    int e = idx / H;
    int h = idx - e * H;
    int src = ei[e];
    int dst = ei[EDGES + e];
    atomicAdd(&d_agg[dst * H + h], ew[e] * d_m[src * H + h]);
}

// ------------------------------------------------------------------
// K3: GRU + fused W2-pre/vt. NPB=2 -> 512 CTAs.
// ------------------------------------------------------------------
__global__ void __launch_bounds__(128)
k3_gru_post(const float* __restrict__ wih,
            const float* __restrict__ whh,
            const float* __restrict__ bih,
            const float* __restrict__ bhh,
            const float* __restrict__ W2,
            const float* __restrict__ b2,
            const float* __restrict__ Wt,
            const float* __restrict__ bt)
{
    int node0 = blockIdx.x * NPB;
    int c = threadIdx.x;
    __shared__ __align__(16) float ag[NPB * H];
    __shared__ __align__(16) float hh[NPB * H];
    __shared__ __align__(16) float vv[NPB * H];

    for (int idx = c; idx < NPB * H; idx += 128) {
        ag[idx] = d_agg[node0 * H + idx];
        hh[idx] = d_h  [node0 * H + idx];
    }
    __syncthreads();

    if (c < H) {
        float air[NPB], aiz[NPB], ain[NPB], ahr[NPB], ahz[NPB], ahn[NPB];
        float br = bih[c], bz = bih[H + c], bn = bih[2 * H + c];
        float cr = bhh[c], cz = bhh[H + c], cn = bhh[2 * H + c];
        #pragma unroll
        for (int n = 0; n < NPB; n++) {
            air[n] = br; aiz[n] = bz; ain[n] = bn;
            ahr[n] = cr; ahz[n] = cz; ahn[n] = cn;
        }
        const float4* wr4 = (const float4*)(wih + (size_t)c * H);
        const float4* wz4 = (const float4*)(wih + (size_t)(H + c) * H);
        const float4* wn4 = (const float4*)(wih + (size_t)(2 * H + c) * H);
        const float4* ur4 = (const float4*)(whh + (size_t)c * H);
        const float4* uz4 = (const float4*)(whh + (size_t)(H + c) * H);
        const float4* un4 = (const float4*)(whh + (size_t)(2 * H + c) * H);

        for (int k = 0; k < H4; k++) {
            float4 wr = wr4[k], wz = wz4[k], wn = wn4[k];
            float4 ur = ur4[k], uz = uz4[k], un = un4[k];
            #pragma unroll
            for (int n = 0; n < NPB; n++) {
                float4 a  = *(const float4*)&ag[n * H + 4 * k];
                float4 hv = *(const float4*)&hh[n * H + 4 * k];
                air[n] = fmaf(a.x, wr.x, air[n]); air[n] = fmaf(a.y, wr.y, air[n]);
                air[n] = fmaf(a.z, wr.z, air[n]); air[n] = fmaf(a.w, wr.w, air[n]);
                aiz[n] = fmaf(a.x, wz.x, aiz[n]); aiz[n] = fmaf(a.y, wz.y, aiz[n]);
                aiz[n] = fmaf(a.z, wz.z, aiz[n]); aiz[n] = fmaf(a.w, wz.w, aiz[n]);
                ain[n] = fmaf(a.x, wn.x, ain[n]); ain[n] = fmaf(a.y, wn.y, ain[n]);
                ain[n] = fmaf(a.z, wn.z, ain[n]); ain[n] = fmaf(a.w, wn.w, ain[n]);
                ahr[n] = fmaf(hv.x, ur.x, ahr[n]); ahr[n] = fmaf(hv.y, ur.y, ahr[n]);
                ahr[n] = fmaf(hv.z, ur.z, ahr[n]); ahr[n] = fmaf(hv.w, ur.w, ahr[n]);
                ahz[n] = fmaf(hv.x, uz.x, ahz[n]); ahz[n] = fmaf(hv.y, uz.y, ahz[n]);
                ahz[n] = fmaf(hv.z, uz.z, ahz[n]); ahz[n] = fmaf(hv.w, uz.w, ahz[n]);
                ahn[n] = fmaf(hv.x, un.x, ahn[n]); ahn[n] = fmaf(hv.y, un.y, ahn[n]);
                ahn[n] = fmaf(hv.z, un.z, ahn[n]); ahn[n] = fmaf(hv.w, un.w, ahn[n]);
            }
        }
        #pragma unroll
        for (int n = 0; n < NPB; n++) {
            float r  = 1.f / (1.f + __expf(-(air[n] + ahr[n])));
            float zg = 1.f / (1.f + __expf(-(aiz[n] + ahz[n])));
            float ng = tanhf(ain[n] + r * ahn[n]);
            float nv = (1.f - zg) * ng + zg * hh[n * H + c];
            vv[n * H + c] = nv;
            d_v[(node0 + n) * H + c] = nv;
        }
    }
    __syncthreads();

    if (c < H) {
        float a2[NPB], a3[NPB];
        float bb2 = b2[c], bbt = bt[c];
        #pragma unroll
        for (int n = 0; n < NPB; n++) { a2[n] = bb2; a3[n] = bbt; }
        const float4* w2r = (const float4*)(W2 + (size_t)c * H);
        const float4* wtr = (const float4*)(Wt + (size_t)c * H);
        for (int k = 0; k < H4; k++) {
            float4 w2 = w2r[k], wt = wtr[k];
            #pragma unroll
            for (int n = 0; n < NPB; n++) {
                float4 v = *(const float4*)&vv[n * H + 4 * k];
                a2[n] = fmaf(v.x, w2.x, a2[n]); a2[n] = fmaf(v.y, w2.y, a2[n]);
                a2[n] = fmaf(v.z, w2.z, a2[n]); a2[n] = fmaf(v.w, w2.w, a2[n]);
                a3[n] = fmaf(v.x, wt.x, a3[n]); a3[n] = fmaf(v.y, wt.y, a3[n]);
                a3[n] = fmaf(v.z, wt.z, a3[n]); a3[n] = fmaf(v.w, wt.w, a3[n]);
            }
        }
        #pragma unroll
        for (int n = 0; n < NPB; n++) {
            d_m [(node0 + n) * H + c] = a2[n];
            d_vt[(node0 + n) * H + c] = a3[n];
        }
    }
}

// ------------------------------------------------------------------
// K4: per-batch light reductions -> d_sh (unchanged)
// ------------------------------------------------------------------
__global__ void k4_attn(const float* __restrict__ W1, const float* __restrict__ b1,
                        const float* __restrict__ qw, const float* __restrict__ qb,
                        const float* __restrict__ W3, const float* __restrict__ b3)
{
    int b = blockIdx.x;
    int t = threadIdx.x;
    __shared__ __align__(16) float sl[H];
    __shared__ float w1s[H];
    __shared__ float as[LSEQ * H];
    __shared__ float alpha[LSEQ];
    __shared__ __align__(16) float sg[H];

    if (t < H) sl[t] = d_v[(b * LSEQ + LSEQ - 1) * H + t];
    __syncthreads();

    if (t < H) {
        float acc = b1[t];
        const float4* w = (const float4*)(W1 + (size_t)t * H);
        for (int k = 0; k < H4; k++) {
            float4 wv = w[k];
            float4 s = *(const float4*)&sl[4 * k];
            acc = fmaf(s.x, wv.x, acc); acc = fmaf(s.y, wv.y, acc);
            acc = fmaf(s.z, wv.z, acc); acc = fmaf(s.w, wv.w, acc);
        }
        w1s[t] = acc;
    }
    __syncthreads();

    for (int idx = t; idx < LSEQ * H; idx += blockDim.x) {
        int l = idx / H, hh2 = idx - l * H;
        float pre = d_m[(b * LSEQ + l) * H + hh2];
        as[idx] = 1.f / (1.f + __expf(-(w1s[hh2] + pre)));
    }
    __syncthreads();

    if (t < LSEQ) {
        float acc = qb[0];
        for (int k = 0; k < H; k++) acc = fmaf(as[t * H + k], qw[k], acc);
        alpha[t] = acc;
    }
    __syncthreads();

    if (t < H) {
        float acc = 0.f;
        for (int l = 0; l < LSEQ; l++) acc = fmaf(alpha[l], d_v[(b * LSEQ + l) * H + t], acc);
        sg[t] = acc;
    }
    __syncthreads();

    if (t < H) {
        float acc = b3[t];
        const float4* w  = (const float4*)(W3 + (size_t)t * 2 * H);
        for (int k = 0; k < H4; k++) {
            float4 wv = w[k];
            float4 s = *(const float4*)&sl[4 * k];
            acc = fmaf(s.x, wv.x, acc); acc = fmaf(s.y, wv.y, acc);
            acc = fmaf(s.z, wv.z, acc); acc = fmaf(s.w, wv.w, acc);
        }
        for (int k = 0; k < H4; k++) {
            float4 wv = w[H4 + k];
            float4 s = *(const float4*)&sg[4 * k];
            acc = fmaf(s.x, wv.x, acc); acc = fmaf(s.y, wv.y, acc);
            acc = fmaf(s.z, wv.z, acc); acc = fmaf(s.w, wv.w, acc);
        }
        d_sh[b * H + t] = acc;
    }
}

// ------------------------------------------------------------------
// P1: bf16 hi/lo split of embed -> [JPAD, KP], zero-padded
// ------------------------------------------------------------------
__global__ void p1_split_embed(const float* __restrict__ embed)
{
    int idx = blockIdx.x * blockDim.x + threadIdx.x;
    if (idx >= JPAD * KP) return;
    int row = idx / KP, k = idx - row * KP;
    float val = (row < NNODE && k < H) ? embed[(size_t)row * H + k] : 0.f;
    __nv_bfloat16 hi = __float2bfloat16(val);
    d_ehi[idx] = hi;
    d_elo[idx] = __float2bfloat16(val - __bfloat162float(hi));
}

// ------------------------------------------------------------------
// P2: B rows [b][n][k]: n<16 -> vt, else v;  plus sh tile [b][k]
// ------------------------------------------------------------------
__global__ void p2_split_b()
{
    int idx = blockIdx.x * blockDim.x + threadIdx.x;
    int nb = BATCH * BROWS * BSTRIDE;
    if (idx < nb) {
        int k = idx % BSTRIDE;
        int r = idx / BSTRIDE;
        int n = r % BROWS;
        int b = r / BROWS;
        float val = 0.f;
        if (k < H)
            val = (n < 16) ? d_vt[(b * LSEQ + n) * H + k]
                           : d_v [(b * LSEQ + (n - 16)) * H + k];
        __nv_bfloat16 hi = __float2bfloat16(val);
        d_bhi[idx] = hi;
        d_blo[idx] = __float2bfloat16(val - __bfloat162float(hi));
    } else {
        int i2 = idx - nb;
        if (i2 < BATCH * BSTRIDE) {
            int k = i2 % BSTRIDE;
            int b = i2 / BSTRIDE;
            float val = (k < H) ? d_sh[b * H + k] : 0.f;
            __nv_bfloat16 hi = __float2bfloat16(val);
            d_shhi[i2] = hi;
            d_shlo[i2] = __float2bfloat16(val - __bfloat162float(hi));
        }
    }
}

// ------------------------------------------------------------------
// K5: HMMA GEMM + softmax epilogue.
//   A-hi frags register-resident; A-lo in smem via ldmatrix per ks.
//   B frags via ldmatrix; 3-deep cp.async pipeline on B fills;
//   no-max softmax epilogue.
// smem layout (bytes):
//   [0, 46080)          3 B buffers (each: hi 7680 | lo 7680)
//   [46080, 76800)      A-lo tile 128 x 120 bf16
//   [76800, 110080)     base floats 128 x 65
// ------------------------------------------------------------------
#define SM_BBUF  0
#define BUFB     15360            // bytes per B buffer
#define SM_ALO   46080
#define SM_BASE  76800
#define SMEM_K5  110080
#define BASE_STRIDE 65
#define BQ1      (BROWS * BSTRIDE)   // 3840 bf16 per split per batch

__global__ void __launch_bounds__(256, 2)
k5_hmma(float* __restrict__ out)
{
    extern __shared__ __align__(16) char dsm[];
    uint32_t smb = smem_u32(dsm);
    float* s_base = (float*)(dsm + SM_BASE);

    int tid  = threadIdx.x;
    int wid  = tid >> 5;
    int lane = tid & 31;
    int grp  = lane >> 2;
    int qid  = lane & 3;
    int tile = blockIdx.x;

    // ---- A-hi fragments, register-resident ----
    uint32_t ahi[KSTEPS][4];
    {
        int r0 = tile * MT + wid * 16 + grp;
        int r1 = r0 + 8;
        #pragma unroll
        for (int ks = 0; ks < KSTEPS; ks++) {
            int k0 = ks * 16 + 2 * qid;
            ahi[ks][0] = *(const uint32_t*)(d_ehi + (size_t)r0 * KP + k0);
            ahi[ks][1] = *(const uint32_t*)(d_ehi + (size_t)r1 * KP + k0);
            ahi[ks][2] = *(const uint32_t*)(d_ehi + (size_t)r0 * KP + k0 + 8);
            ahi[ks][3] = *(const uint32_t*)(d_ehi + (size_t)r1 * KP + k0 + 8);
        }
    }

    // ---- stage A-lo tile into smem (128 x 112 bf16, stride 120) ----
    {
        const __nv_bfloat16* src = d_elo + (size_t)tile * MT * KP;
        // 1792 chunks of 16B: row = c/14, col16 = c%14
        for (int c = tid; c < MT * 14; c += 256) {
            int row = c / 14, cc = c - row * 14;
            uint32_t dst = smb + SM_ALO + row * 240 + cc * 16;
            CP_ASYNC16(dst, (const char*)(src + (size_t)row * KP) + cc * 16);
        }
        // stage sh tiles (hi, lo) into B-buffer region for phase 0
        for (int c = tid; c < 960; c += 256) {   // 64*120*2B = 15360B = 960 chunks
            uint32_t dst = smb + SM_BBUF + c * 16;
            CP_ASYNC16(dst, (const char*)d_shhi + c * 16);
            CP_ASYNC16(dst + BUFB, (const char*)d_shlo + c * 16);
        }
        CP_COMMIT();
        CP_WAIT0();
    }
    __syncthreads();

    // ldmatrix addresses
    uint32_t alo_addr = smb + SM_ALO + (wid * 16 + (lane & 15)) * 240
                        + ((lane >> 4) * 8) * 2;             // + ks*32 per step
    uint32_t brow_off = lane * 240;                          // B tile: n = lane

    // ================= PHASE 0: base GEMM (E . SH^T) =================
    {
        const __nv_bfloat16* Bh = (const __nv_bfloat16*)(dsm + SM_BBUF);
        const __nv_bfloat16* Bl = (const __nv_bfloat16*)(dsm + SM_BBUF + BUFB);
        float Db[8][4];
        #pragma unroll
        for (int nt = 0; nt < 8; nt++)
            { Db[nt][0] = 0.f; Db[nt][1] = 0.f; Db[nt][2] = 0.f; Db[nt][3] = 0.f; }

        #pragma unroll
        for (int ks = 0; ks < KSTEPS; ks++) {
            int kb = ks * 16 + 2 * qid;
            uint32_t al[4];
            LDSM4(al[0], al[1], al[2], al[3], alo_addr + ks * 32);
            #pragma unroll
            for (int nt = 0; nt < 8; nt++) {
                int n = nt * 8 + grp;
                uint32_t bh0 = *(const uint32_t*)(Bh + n * BSTRIDE + kb);
                uint32_t bh1 = *(const uint32_t*)(Bh + n * BSTRIDE + kb + 8);
                uint32_t bl0 = *(const uint32_t*)(Bl + n * BSTRIDE + kb);
                uint32_t bl1 = *(const uint32_t*)(Bl + n * BSTRIDE + kb + 8);
                MMA16816(Db[nt], ahi[ks], bh0, bh1);
                MMA16816(Db[nt], ahi[ks], bl0, bl1);
                MMA16816(Db[nt], al,      bh0, bh1);
            }
        }
        int r0 = wid * 16 + grp, r1 = r0 + 8;
        #pragma unroll
        for (int nt = 0; nt < 8; nt++) {
            int c0 = nt * 8 + 2 * qid;
            s_base[r0 * BASE_STRIDE + c0]     = Db[nt][0];
            s_base[r0 * BASE_STRIDE + c0 + 1] = Db[nt][1];
            s_base[r1 * BASE_STRIDE + c0]     = Db[nt][2];
            s_base[r1 * BASE_STRIDE + c0 + 1] = Db[nt][3];
        }
        __syncthreads();
    }

    // ---- prime cp.async pipeline: batches 0 and 1 ----
    #pragma unroll
    for (int pb = 0; pb < 2; pb++) {
        uint32_t dst = smb + SM_BBUF + pb * BUFB;
        const char* sh = (const char*)(d_bhi + (size_t)pb * BQ1);
        const char* sl = (const char*)(d_blo + (size_t)pb * BQ1);
        for (int c = tid; c < 480; c += 256) {
            CP_ASYNC16(dst + c * 16, sh + c * 16);
            CP_ASYNC16(dst + 7680 + c * 16, sl + c * 16);
        }
        CP_COMMIT();
    }
    CP_WAIT1();           // batch 0 ready
    __syncthreads();

    int rl0 = wid * 16 + grp;
    int j0 = tile * MT + rl0;
    int j1 = j0 + 8;

    #pragma unroll 1
    for (int b = 0; b < BATCH; b++) {
        uint32_t bufb = smb + SM_BBUF + (b % 3) * BUFB;

        // ---- MMA mainloop ----
        float D[NTL][4];
        #pragma unroll
        for (int nt = 0; nt < NTL; nt++)
            { D[nt][0] = 0.f; D[nt][1] = 0.f; D[nt][2] = 0.f; D[nt][3] = 0.f; }

        #pragma unroll
        for (int ks = 0; ks < KSTEPS; ks++) {
            uint32_t al[4], bh0[4], bh1[4], bl0[4], bl1[4];
            LDSM4(al[0], al[1], al[2], al[3], alo_addr + ks * 32);
            LDSM4(bh0[0], bh0[1], bh0[2], bh0[3], bufb + brow_off + ks * 32);
            LDSM4(bh1[0], bh1[1], bh1[2], bh1[3], bufb + brow_off + ks * 32 + 16);
            LDSM4(bl0[0], bl0[1], bl0[2], bl0[3], bufb + 7680 + brow_off + ks * 32);
            LDSM4(bl1[0], bl1[1], bl1[2], bl1[3], bufb + 7680 + brow_off + ks * 32 + 16);
            #pragma unroll
            for (int nt = 0; nt < NTL; nt++) MMA16816(D[nt], ahi[ks], bh0[nt], bh1[nt]);
            #pragma unroll
            for (int nt = 0; nt < NTL; nt++) MMA16816(D[nt], ahi[ks], bl0[nt], bl1[nt]);
            #pragma unroll
            for (int nt = 0; nt < NTL; nt++) MMA16816(D[nt], al,      bh0[nt], bh1[nt]);
        }

        // ---- issue prefetch for batch b+2 (always commit a group) ----
        if (b + 2 < BATCH) {
            uint32_t dst = smb + SM_BBUF + ((b + 2) % 3) * BUFB;
            const char* sh = (const char*)(d_bhi + (size_t)(b + 2) * BQ1);
            const char* sl = (const char*)(d_blo + (size_t)(b + 2) * BQ1);
            for (int c = tid; c < 480; c += 256) {
                CP_ASYNC16(dst + c * 16, sh + c * 16);
                CP_ASYNC16(dst + 7680 + c * 16, sl + c * 16);
            }
        }
        CP_COMMIT();

        // ---- epilogue (no-max softmax; logits are O(1) here) ----
        {
            float base0 = s_base[rl0 * BASE_STRIDE + b];
            float base1 = s_base[(rl0 + 8) * BASE_STRIDE + b];

            float e00 = __expf(D[0][0]), e01 = __expf(D[0][1]);
            float e10 = __expf(D[1][0]), e11 = __expf(D[1][1]);
            float es0 = (e00 + e01) + (e10 + e11);
            float ws0 = fmaf(e00, D[2][0], fmaf(e01, D[2][1],
                        fmaf(e10, D[3][0], e11 * D[3][1])));

            float f00 = __expf(D[0][2]), f01 = __expf(D[0][3]);
            float f10 = __expf(D[1][2]), f11 = __expf(D[1][3]);
            float es1 = (f00 + f01) + (f10 + f11);
            float ws1 = fmaf(f00, D[2][2], fmaf(f01, D[2][3],
                        fmaf(f10, D[3][2], f11 * D[3][3])));

            es0 += __shfl_xor_sync(0xffffffffu, es0, 1);
            ws0 += __shfl_xor_sync(0xffffffffu, ws0, 1);
            es1 += __shfl_xor_sync(0xffffffffu, es1, 1);
            ws1 += __shfl_xor_sync(0xffffffffu, ws1, 1);
            es0 += __shfl_xor_sync(0xffffffffu, es0, 2);
            ws0 += __shfl_xor_sync(0xffffffffu, ws0, 2);
            es1 += __shfl_xor_sync(0xffffffffu, es1, 2);
            ws1 += __shfl_xor_sync(0xffffffffu, ws1, 2);

            if (qid == 0) {
                if (j0 < NNODE) out[(size_t)b * NNODE + j0] = base0 + ws0 / es0;
                if (j1 < NNODE) out[(size_t)b * NNODE + j1] = base1 + ws1 / es1;
            }
        }

        CP_WAIT1();        // batch b+1's fill complete (b+2 may still fly)
        __syncthreads();
    }
}

// ------------------------------------------------------------------
extern "C" void kernel_launch(void* const* d_in, const int* in_sizes, int n_in,
                              void* d_out, int out_size)
{
    const int*   x     = (const int*)  d_in[0];
    const int*   ei    = (const int*)  d_in[1];
    const float* ew    = (const float*)d_in[2];
    // d_in[3] = batch (unused)
    const float* embed = (const float*)d_in[4];
    const float* ggc   = (const float*)d_in[5];
    const float* wih   = (const float*)d_in[6];
    const float* whh   = (const float*)d_in[7];
    const float* bih   = (const float*)d_in[8];
    const float* bhh   = (const float*)d_in[9];
    const float* W1    = (const float*)d_in[10];
    const float* b1    = (const float*)d_in[11];
    const float* W2    = (const float*)d_in[12];
    const float* b2    = (const float*)d_in[13];
    const float* Wt    = (const float*)d_in[14];
    const float* bt    = (const float*)d_in[15];
    const float* qw    = (const float*)d_in[16];
    const float* qb    = (const float*)d_in[17];
    const float* W3    = (const float*)d_in[18];
    const float* b3    = (const float*)d_in[19];
    float* out = (float*)d_out;

    cudaFuncSetAttribute(k5_hmma, cudaFuncAttributeMaxDynamicSharedMemorySize, SMEM_K5);

    k1_gather_m<<<NNODES, 128>>>(x, embed, ggc);
    k2_scatter <<<(EDGES * H + 255) / 256, 256>>>(ei, ew);
    p1_split_embed<<<(JPAD * KP + 255) / 256, 256>>>(embed);
    k3_gru_post<<<NNODES / NPB, 128>>>(wih, whh, bih, bhh, W2, b2, Wt, bt);
    k4_attn    <<<BATCH, 128>>>(W1, b1, qw, qb, W3, b3);
    p2_split_b <<<(BATCH * BROWS * BSTRIDE + BATCH * BSTRIDE + 255) / 256, 256>>>();
    k5_hmma    <<<NTILES, 256, SMEM_K5>>>(out);
}